// round 11
// baseline (speedup 1.0000x reference)
#include <cuda_runtime.h>
#include <cuda_bf16.h>
#include <math.h>

// ---------------- problem constants ----------------
#define L     131072
#define C     192
#define NHD   6
#define HD    32
#define NWIN  256
#define NP    64
#define HID   768
#define DD    32
#define HHH   64
#define WWW   64

// ---------------- scratch ----------------
__device__ __nv_bfloat16 g_xnb [L * C];
__device__ __nv_bfloat16 g_qb  [L * C];
__device__ __nv_bfloat16 g_kb  [NWIN * NHD * NP * HD];
__device__ __nv_bfloat16 g_vb2 [NWIN * NHD * NP * HD];
__device__ __nv_bfloat16 g_ob  [L * C];
__device__ float         g_x1  [L * C];
__device__ __nv_bfloat16 g_hidb[L * HID];
__device__ __nv_bfloat16 g_hdnb[L * HID];
__device__ __nv_bfloat16 g_qkvT[256 * C];
__device__ float         g_qkvb[256];
__device__ __nv_bfloat16 g_pwT [C * C];
__device__ __nv_bfloat16 g_f1wT[HID * C];
__device__ __nv_bfloat16 g_f2wT[C * HID];

__device__ __forceinline__ float gelu_f(float v) {
    return 0.5f * v * (1.0f + erff(v * 0.70710678118654752f));
}

__device__ __forceinline__ void mma_bf16(float* d, const unsigned* a, const unsigned* b) {
    asm volatile(
        "mma.sync.aligned.m16n8k16.row.col.f32.bf16.bf16.f32 "
        "{%0,%1,%2,%3},{%4,%5,%6,%7},{%8,%9},{%0,%1,%2,%3};"
        : "+f"(d[0]), "+f"(d[1]), "+f"(d[2]), "+f"(d[3])
        : "r"(a[0]), "r"(a[1]), "r"(a[2]), "r"(a[3]), "r"(b[0]), "r"(b[1]));
}

#define LDSM_X4(r0, r1, r2, r3, addr) \
    asm volatile("ldmatrix.sync.aligned.m8n8.x4.shared.b16 {%0,%1,%2,%3}, [%4];" \
                 : "=r"(r0), "=r"(r1), "=r"(r2), "=r"(r3) : "r"(addr))

#define CP16(dst_smem_u32, src_ptr) \
    asm volatile("cp.async.cg.shared.global [%0], [%1], 16;\n" \
                 :: "r"(dst_smem_u32), "l"(src_ptr))
#define CP_COMMIT() asm volatile("cp.async.commit_group;\n" ::: "memory")
#define CP_WAIT1()  asm volatile("cp.async.wait_group 1;\n" ::: "memory")

__device__ __forceinline__ float4 ldbf4(const __nv_bfloat16* p) {
    uint2 u = *(const uint2*)p;
    float2 a = __bfloat1622float2(*(__nv_bfloat162*)&u.x);
    float2 b = __bfloat1622float2(*(__nv_bfloat162*)&u.y);
    return make_float4(a.x, a.y, b.x, b.y);
}
__device__ __forceinline__ float2 ldbf2(const __nv_bfloat16* p) {
    unsigned u = *(const unsigned*)p;
    return __bfloat1622float2(*(__nv_bfloat162*)&u);
}
__device__ __forceinline__ unsigned packbf(float a, float b) {
    __nv_bfloat162 t = __floats2bfloat162_rn(a, b);
    return *(unsigned*)&t;
}

// ------------- prep ------------
#define PREP_R0 (256 * 192)
#define PREP_R1 (PREP_R0 + 192 * 192)
#define PREP_R2 (PREP_R1 + 768 * 192)
#define PREP_R3 (PREP_R2 + 192 * 768)
__global__ void prep_kernel(const float* __restrict__ q_w, const float* __restrict__ q_b,
                            const float* __restrict__ kv_w, const float* __restrict__ kv_b,
                            const float* __restrict__ p_w, const float* __restrict__ f1w,
                            const float* __restrict__ f2w)
{
    const float qscale = 0.17677669529663687f;
    int id = blockIdx.x * 256 + threadIdx.x;
    if (id < 256) {
        float b = 0.f;
        if (id < 192)      b = q_b[id] * qscale;
        else if (id < 240) b = kv_b[id - 192];
        g_qkvb[id] = b;
    }
    if (id < PREP_R0) {
        int n = id / 192, k = id % 192;
        float v = 0.f;
        if (n < 192)      v = q_w[k * 192 + n] * qscale;
        else if (n < 240) v = kv_w[k * 48 + (n - 192)];
        g_qkvT[n * 192 + k] = __float2bfloat16(v);
    } else if (id < PREP_R1) {
        int e = id - PREP_R0, n = e / 192, k = e % 192;
        g_pwT[n * 192 + k] = __float2bfloat16(p_w[k * 192 + n]);
    } else if (id < PREP_R2) {
        int e = id - PREP_R1, n = e / 192, k = e % 192;
        g_f1wT[n * 192 + k] = __float2bfloat16(f1w[k * 768 + n]);
    } else if (id < PREP_R3) {
        int e = id - PREP_R2, n = e / 768, k = e % 768;
        g_f2wT[n * 768 + k] = __float2bfloat16(f2w[k * 192 + n]);
    }
}

// ---------------- LayerNorm (fp32 in, bf16 out) — LN1 only -----------------
__global__ void ln_kernel(const float* __restrict__ x, const float* __restrict__ g,
                          const float* __restrict__ b, __nv_bfloat16* __restrict__ y)
{
    int lane = threadIdx.x & 31;
    int wi   = threadIdx.x >> 5;
    int l    = blockIdx.x * 8 + wi;
    const float* row = x + (size_t)l * C;
    float v[6];
    float s = 0.f, ss = 0.f;
#pragma unroll
    for (int i = 0; i < 6; i++) {
        v[i] = row[lane + 32 * i];
        s  += v[i];
        ss += v[i] * v[i];
    }
#pragma unroll
    for (int off = 16; off > 0; off >>= 1) {
        s  += __shfl_xor_sync(0xffffffffu, s,  off);
        ss += __shfl_xor_sync(0xffffffffu, ss, off);
    }
    float mean = s * (1.0f / C);
    float var  = ss * (1.0f / C) - mean * mean;
    float inv  = rsqrtf(var + 1e-5f);
    __nv_bfloat16* yr = y + (size_t)l * C;
#pragma unroll
    for (int i = 0; i < 6; i++) {
        int c = lane + 32 * i;
        yr[c] = __float2bfloat16((v[i] - mean) * inv * g[c] + b[c]);
    }
}

// -------- fused q+kv GEMM: 128x256 single col-block, 512 thr, 16 warps -----
#define QKV_SMEM_BYTES ((3 * (128 * 20 + 256 * 20)) * 4)
__global__ void __launch_bounds__(512)
gemm_qkv(const __nv_bfloat16* __restrict__ A,
         __nv_bfloat16* __restrict__ qout, __nv_bfloat16* __restrict__ ko,
         __nv_bfloat16* __restrict__ vo)
{
    extern __shared__ unsigned gsm[];
    unsigned* As = gsm;                    // [3][128][20]
    unsigned* Bs = gsm + 3 * 128 * 20;     // [3][256][20]
    const int K = 192;

    const int tid  = threadIdx.x;
    const int lane = tid & 31, warp = tid >> 5;
    const int wm = warp & 3, wn = warp >> 2;   // warp tile 32(m) x 64(n)
    const int row0 = blockIdx.y * 128;

    float acc[2][8][4];
#pragma unroll
    for (int i = 0; i < 2; i++)
#pragma unroll
        for (int j = 0; j < 8; j++)
#pragma unroll
            for (int t = 0; t < 4; t++) acc[i][j][t] = 0.f;

    const unsigned sA = (unsigned)__cvta_generic_to_shared(As);
    const unsigned sB = (unsigned)__cvta_generic_to_shared(Bs);
    const __nv_bfloat16* Wt = g_qkvT;

    auto load_tile = [&](int kt, int st) {
        unsigned aOff = sA + (unsigned)(st * 128 * 20) * 4;
        {   // A: 512 chunks, 1/thread
            int r = tid >> 2, wc = (tid & 3) * 4;
            CP16(aOff + (unsigned)(r * 20 + wc) * 4,
                 A + (size_t)(row0 + r) * K + kt + wc * 2);
        }
        unsigned bOff = sB + (unsigned)(st * 256 * 20) * 4;
#pragma unroll
        for (int i = 0; i < 2; i++) {   // B: 1024 chunks, 2/thread
            int id = tid + i * 512;
            int r = id >> 2, wc = (id & 3) * 4;
            CP16(bOff + (unsigned)(r * 20 + wc) * 4,
                 Wt + (size_t)r * K + kt + wc * 2);
        }
        CP_COMMIT();
    };

    load_tile(0, 0);
    load_tile(32, 1);

    const int a_row_sel = lane & 15;
    const int a_k_sel   = (lane >> 4) * 4;
    const int b_row_sel = (lane & 7) + (lane >> 4) * 8;
    const int b_k_sel   = ((lane >> 3) & 1) * 4;
    const int rb0 = wm * 32, cb0 = wn * 64;

    int st = 0;
    for (int t = 0; t < 6; t++) {
        CP_WAIT1();
        __syncthreads();
        if (t + 2 < 6) {
            int st2 = st + 2; if (st2 >= 3) st2 -= 3;
            load_tile((t + 2) << 5, st2);
        }
        const unsigned sAst = sA + (unsigned)(st * 128 * 20) * 4;
        const unsigned sBst = sB + (unsigned)(st * 256 * 20) * 4;
#pragma unroll
        for (int ks = 0; ks < 2; ks++) {
            const int koff = ks * 8;
            unsigned af[2][4], bf[8][2];
#pragma unroll
            for (int mi = 0; mi < 2; mi++) {
                unsigned addr = sAst +
                    (unsigned)(((rb0 + mi * 16 + a_row_sel) * 20 + a_k_sel + koff) * 4);
                LDSM_X4(af[mi][0], af[mi][1], af[mi][2], af[mi][3], addr);
            }
#pragma unroll
            for (int g = 0; g < 4; g++) {
                unsigned r0, r1, r2, r3;
                unsigned addr = sBst +
                    (unsigned)(((cb0 + g * 16 + b_row_sel) * 20 + b_k_sel + koff) * 4);
                LDSM_X4(r0, r1, r2, r3, addr);
                bf[g * 2 + 0][0] = r0; bf[g * 2 + 0][1] = r1;
                bf[g * 2 + 1][0] = r2; bf[g * 2 + 1][1] = r3;
            }
#pragma unroll
            for (int mi = 0; mi < 2; mi++)
#pragma unroll
                for (int ni = 0; ni < 8; ni++)
                    mma_bf16(acc[mi][ni], af[mi], bf[ni]);
        }
        if (++st == 3) st = 0;
    }

    const int rq = lane >> 2, tq = lane & 3;
    const int crow0 = row0 + wm * 32 + rq;
    const int ccol  = wn * 64 + tq * 2;
#pragma unroll
    for (int mi = 0; mi < 2; mi++) {
#pragma unroll
        for (int half = 0; half < 2; half++) {
            int row = crow0 + mi * 16 + half * 8;
#pragma unroll
            for (int ni = 0; ni < 8; ni++) {
                int col = ccol + ni * 8;
                float v0 = acc[mi][ni][half * 2 + 0] + g_qkvb[col];
                float v1 = acc[mi][ni][half * 2 + 1] + g_qkvb[col + 1];
                if (col < 192) {
                    *(unsigned*)(qout + (size_t)row * 192 + col) = packbf(v0, v1);
                } else if (col < 240) {
                    int j = col - 192, jg = j >> 2, tt = j & 3;
                    __nv_bfloat16* dst = (jg < 6) ? ko : vo;
                    int head = (jg < 6) ? jg : jg - 6;
                    int z = row >> 12, y = (row >> 6) & 63, xq = row & 63;
                    int win = ((z >> 3) << 6) | ((y >> 3) << 3) | (xq >> 3);
                    int m = (((z & 7) >> 1) << 4) | (((y & 7) >> 1) << 2) | ((xq & 7) >> 1);
                    int sub = ((z & 1) << 2) | ((y & 1) << 1) | (xq & 1);
                    *(unsigned*)&dst[(((size_t)(win * 6 + head)) * 64 + m) * 32 + sub * 4 + tt] =
                        packbf(v0, v1);
                }
            }
        }
    }
}

// -------- wide GEMM 128x192, 512 thr; EPI: 1=+res fp32, 2=gelu bf16,
//          3 = +res -> x1 fp32 AND fused LayerNorm -> bf16 xout --------------
#define G192_SMEM_BYTES ((3 * (128 * 20 + 192 * 20)) * 4)
template <int EPI>
__global__ void __launch_bounds__(512)
gemm192(const __nv_bfloat16* __restrict__ A, const __nv_bfloat16* __restrict__ Wt,
        const float* __restrict__ bias, const float* __restrict__ res,
        float* __restrict__ Cf, __nv_bfloat16* __restrict__ Cb,
        const float* __restrict__ lng, const float* __restrict__ lnb,
        int N, int K)
{
    extern __shared__ unsigned gsm[];
    unsigned* As = gsm;
    unsigned* Bs = gsm + 3 * 128 * 20;

    const int tid  = threadIdx.x;
    const int lane = tid & 31, warp = tid >> 5;
    const int wm = warp & 3, wn = warp >> 2;
    const int row0 = blockIdx.y * 128, col0 = blockIdx.x * 192;

    float acc[2][6][4];
#pragma unroll
    for (int i = 0; i < 2; i++)
#pragma unroll
        for (int j = 0; j < 6; j++)
#pragma unroll
            for (int t = 0; t < 4; t++) acc[i][j][t] = 0.f;

    const unsigned sA = (unsigned)__cvta_generic_to_shared(As);
    const unsigned sB = (unsigned)__cvta_generic_to_shared(Bs);
    const int ntiles = K >> 5;

    auto load_tile = [&](int kt, int st) {
        unsigned aOff = sA + (unsigned)(st * 128 * 20) * 4;
        {
            int r = tid >> 2, wc = (tid & 3) * 4;
            CP16(aOff + (unsigned)(r * 20 + wc) * 4,
                 A + (size_t)(row0 + r) * K + kt + wc * 2);
        }
        unsigned bOff = sB + (unsigned)(st * 192 * 20) * 4;
        {
            int r = tid >> 2, wc = (tid & 3) * 4;
            CP16(bOff + (unsigned)(r * 20 + wc) * 4,
                 Wt + (size_t)(col0 + r) * K + kt + wc * 2);
            if (tid < 256) {
                int id = tid + 512;
                int r2 = id >> 2, wc2 = (id & 3) * 4;
                CP16(bOff + (unsigned)(r2 * 20 + wc2) * 4,
                     Wt + (size_t)(col0 + r2) * K + kt + wc2 * 2);
            }
        }
        CP_COMMIT();
    };

    load_tile(0, 0);
    load_tile(32, 1);

    const int a_row_sel = lane & 15;
    const int a_k_sel   = (lane >> 4) * 4;
    const int b_row_sel = (lane & 7) + (lane >> 4) * 8;
    const int b_k_sel   = ((lane >> 3) & 1) * 4;
    const int rb0 = wm * 32, cb0 = wn * 48;

    int st = 0;
    for (int t = 0; t < ntiles; t++) {
        CP_WAIT1();
        __syncthreads();
        if (t + 2 < ntiles) {
            int st2 = st + 2; if (st2 >= 3) st2 -= 3;
            load_tile((t + 2) << 5, st2);
        }
        const unsigned sAst = sA + (unsigned)(st * 128 * 20) * 4;
        const unsigned sBst = sB + (unsigned)(st * 192 * 20) * 4;
#pragma unroll
        for (int ks = 0; ks < 2; ks++) {
            const int koff = ks * 8;
            unsigned af[2][4], bf[6][2];
#pragma unroll
            for (int mi = 0; mi < 2; mi++) {
                unsigned addr = sAst +
                    (unsigned)(((rb0 + mi * 16 + a_row_sel) * 20 + a_k_sel + koff) * 4);
                LDSM_X4(af[mi][0], af[mi][1], af[mi][2], af[mi][3], addr);
            }
#pragma unroll
            for (int g = 0; g < 3; g++) {
                unsigned r0, r1, r2, r3;
                unsigned addr = sBst +
                    (unsigned)(((cb0 + g * 16 + b_row_sel) * 20 + b_k_sel + koff) * 4);
                LDSM_X4(r0, r1, r2, r3, addr);
                bf[g * 2 + 0][0] = r0; bf[g * 2 + 0][1] = r1;
                bf[g * 2 + 1][0] = r2; bf[g * 2 + 1][1] = r3;
            }
#pragma unroll
            for (int mi = 0; mi < 2; mi++)
#pragma unroll
                for (int ni = 0; ni < 6; ni++)
                    mma_bf16(acc[mi][ni], af[mi], bf[ni]);
        }
        if (++st == 3) st = 0;
    }

    const int rq = lane >> 2, tq = lane & 3;
    const int crow0 = row0 + wm * 32 + rq;
    const int ccol  = col0 + wn * 48 + tq * 2;

    if (EPI == 3) {
        __syncthreads();
        float* st_s  = (float*)gsm;
        float* st_ss = (float*)gsm + 512;
#pragma unroll
        for (int mi = 0; mi < 2; mi++)
#pragma unroll
            for (int half = 0; half < 2; half++) {
                int row = crow0 + mi * 16 + half * 8;
                float s = 0.f, ss = 0.f;
#pragma unroll
                for (int ni = 0; ni < 6; ni++) {
                    int col = ccol + ni * 8;
                    float2 rv = *(const float2*)(res + (size_t)row * 192 + col);
                    float v0 = acc[mi][ni][half * 2 + 0] + bias[col]     + rv.x;
                    float v1 = acc[mi][ni][half * 2 + 1] + bias[col + 1] + rv.y;
                    acc[mi][ni][half * 2 + 0] = v0;
                    acc[mi][ni][half * 2 + 1] = v1;
                    s += v0 + v1; ss += v0 * v0 + v1 * v1;
                }
                s  += __shfl_xor_sync(0xffffffffu, s, 1);
                s  += __shfl_xor_sync(0xffffffffu, s, 2);
                ss += __shfl_xor_sync(0xffffffffu, ss, 1);
                ss += __shfl_xor_sync(0xffffffffu, ss, 2);
                if (tq == 0) {
                    int rowl = wm * 32 + mi * 16 + half * 8 + rq;
                    st_s [rowl * 4 + wn] = s;
                    st_ss[rowl * 4 + wn] = ss;
                }
            }
        __syncthreads();
#pragma unroll
        for (int mi = 0; mi < 2; mi++)
#pragma unroll
            for (int half = 0; half < 2; half++) {
                int rowl = wm * 32 + mi * 16 + half * 8 + rq;
                int row  = row0 + rowl;
                float S  = st_s[rowl*4] + st_s[rowl*4+1] + st_s[rowl*4+2] + st_s[rowl*4+3];
                float SS = st_ss[rowl*4] + st_ss[rowl*4+1] + st_ss[rowl*4+2] + st_ss[rowl*4+3];
                float mean = S * (1.0f / 192.0f);
                float var  = SS * (1.0f / 192.0f) - mean * mean;
                float inv  = rsqrtf(var + 1e-5f);
#pragma unroll
                for (int ni = 0; ni < 6; ni++) {
                    int col = ccol + ni * 8;
                    float v0 = acc[mi][ni][half * 2 + 0];
                    float v1 = acc[mi][ni][half * 2 + 1];
                    *(float2*)(Cf + (size_t)row * 192 + col) = make_float2(v0, v1);
                    float n0 = (v0 - mean) * inv * lng[col]     + lnb[col];
                    float n1 = (v1 - mean) * inv * lng[col + 1] + lnb[col + 1];
                    *(unsigned*)(Cb + (size_t)row * 192 + col) = packbf(n0, n1);
                }
            }
        return;
    }

#pragma unroll
    for (int mi = 0; mi < 2; mi++) {
#pragma unroll
        for (int half = 0; half < 2; half++) {
            int row = crow0 + mi * 16 + half * 8;
#pragma unroll
            for (int ni = 0; ni < 6; ni++) {
                int col = ccol + ni * 8;
                float v0 = acc[mi][ni][half * 2 + 0] + bias[col];
                float v1 = acc[mi][ni][half * 2 + 1] + bias[col + 1];
                if (EPI == 1) {
                    float2 rv = *(const float2*)(res + (size_t)row * N + col);
                    *(float2*)(Cf + (size_t)row * N + col) =
                        make_float2(v0 + rv.x, v1 + rv.y);
                } else {
                    *(unsigned*)(Cb + (size_t)row * N + col) =
                        packbf(gelu_f(v0), gelu_f(v1));
                }
            }
        }
    }
}

// ---------------- attention: full bf16, m16n8k16 ----------------
#define ATTN_SMEM_WORDS (64*20 + 32*36 + 128*20 + 8*16*36 + 343)
__global__ void __launch_bounds__(256)
attn_mma_kernel(const __nv_bfloat16* __restrict__ q, const __nv_bfloat16* __restrict__ kbuf,
                const __nv_bfloat16* __restrict__ vbuf, const float* __restrict__ btab,
                __nv_bfloat16* __restrict__ o)
{
    extern __shared__ unsigned sm[];
    unsigned* Ks = sm;
    unsigned* Vt = Ks + 64 * 20;
    unsigned* Qs = Vt + 32 * 36;
    unsigned* Pw = Qs + 128 * 20;
    float*    bt = (float*)(Pw + 8 * 16 * 36);

    const int win  = blockIdx.x / NHD;
    const int head = blockIdx.x % NHD;
    const int tid = threadIdx.x, lane = tid & 31, w = tid >> 5;
    const int rq = lane >> 2, tq = lane & 3;

    const __nv_bfloat16* kb = kbuf + (size_t)(win * NHD + head) * NP * HD;
    const __nv_bfloat16* vb = vbuf + (size_t)(win * NHD + head) * NP * HD;
    for (int i = tid; i < 64 * 16; i += 256) {
        int m = i >> 4, wp = i & 15;
        Ks[m * 20 + wp] = ((const unsigned*)kb)[i];
    }
    for (int i = tid; i < 32 * 32; i += 256) {
        int c = i >> 5, mp = i & 31;
        Vt[c * 36 + mp] = packbf(__bfloat162float(vb[(2 * mp) * 32 + c]),
                                 __bfloat162float(vb[(2 * mp + 1) * 32 + c]));
    }
    for (int i = tid; i < 343; i += 256) bt[i] = btab[i * NHD + head];

    const int wz = win >> 6, wy = (win >> 3) & 7, wx = win & 7;
    const int wbase = wz * 32768 + wy * 512 + wx * 8;
    unsigned* Pme = Pw + w * 16 * 36;

#pragma unroll 1
    for (int p = 0; p < 4; p++) {
        __syncthreads();
#pragma unroll
        for (int i = 0; i < 2; i++) {
            int idx = tid + i * 256;
            int r = idx >> 2, wc = (idx & 3) * 4;
            int n = p * 128 + r;
            int l = wbase + (n >> 6) * 4096 + ((n >> 3) & 7) * 64 + (n & 7);
            uint4 v4 = *(const uint4*)(q + (size_t)l * C + head * HD + wc * 2);
            *(uint4*)&Qs[r * 20 + wc] = v4;
        }
        __syncthreads();

        float s[8][4];
#pragma unroll
        for (int j = 0; j < 8; j++)
#pragma unroll
            for (int t = 0; t < 4; t++) s[j][t] = 0.f;

        const unsigned* Qrow = Qs + (w * 16 + rq) * 20;
#pragma unroll
        for (int kc = 0; kc < 2; kc++) {
            const int kw = kc * 8;
            unsigned a[4];
            a[0] = Qrow[kw + tq];
            a[1] = Qrow[8 * 20 + kw + tq];
            a[2] = Qrow[kw + tq + 4];
            a[3] = Qrow[8 * 20 + kw + tq + 4];
#pragma unroll
            for (int j = 0; j < 8; j++) {
                unsigned b[2];
                const unsigned* Kr = Ks + (j * 8 + rq) * 20 + kw + tq;
                b[0] = Kr[0];
                b[1] = Kr[4];
                mma_bf16(s[j], a, b);
            }
        }

        const int n0 = p * 128 + w * 16 + rq;
        const int n1 = n0 + 8;
        int qb0, qb1;
        {
            int zz = n0 >> 6, yy = (n0 >> 3) & 7, xx = n0 & 7;
            qb0 = ((zz >> 1) + 3) * 49 + ((yy >> 1) + 3) * 7 + (xx >> 1) + 3;
            zz = n1 >> 6; yy = (n1 >> 3) & 7; xx = n1 & 7;
            qb1 = ((zz >> 1) + 3) * 49 + ((yy >> 1) + 3) * 7 + (xx >> 1) + 3;
        }
        float mx0 = -1e30f, mx1 = -1e30f;
#pragma unroll
        for (int j = 0; j < 8; j++) {
#pragma unroll
            for (int s2 = 0; s2 < 2; s2++) {
                int m = j * 8 + tq * 2 + s2;
                int koff = (m >> 4) * 49 + ((m >> 2) & 3) * 7 + (m & 3);
                s[j][s2]     += bt[qb0 - koff];
                s[j][2 + s2] += bt[qb1 - koff];
                mx0 = fmaxf(mx0, s[j][s2]);
                mx1 = fmaxf(mx1, s[j][2 + s2]);
            }
        }
        mx0 = fmaxf(mx0, __shfl_xor_sync(0xffffffffu, mx0, 1));
        mx0 = fmaxf(mx0, __shfl_xor_sync(0xffffffffu, mx0, 2));
        mx1 = fmaxf(mx1, __shfl_xor_sync(0xffffffffu, mx1, 1));
        mx1 = fmaxf(mx1, __shfl_xor_sync(0xffffffffu, mx1, 2));
        float sum0 = 0.f, sum1 = 0.f;
#pragma unroll
        for (int j = 0; j < 8; j++) {
#pragma unroll
            for (int s2 = 0; s2 < 2; s2++) {
                s[j][s2]     = __expf(s[j][s2]     - mx0);
                s[j][2 + s2] = __expf(s[j][2 + s2] - mx1);
                sum0 += s[j][s2];
                sum1 += s[j][2 + s2];
            }
        }
        sum0 += __shfl_xor_sync(0xffffffffu, sum0, 1);
        sum0 += __shfl_xor_sync(0xffffffffu, sum0, 2);
        sum1 += __shfl_xor_sync(0xffffffffu, sum1, 1);
        sum1 += __shfl_xor_sync(0xffffffffu, sum1, 2);
        const float inv0 = 1.0f / sum0, inv1 = 1.0f / sum1;

#pragma unroll
        for (int j = 0; j < 8; j++) {
            Pme[rq * 36 + j * 4 + tq]       = packbf(s[j][0] * inv0, s[j][1] * inv0);
            Pme[(rq + 8) * 36 + j * 4 + tq] = packbf(s[j][2] * inv1, s[j][3] * inv1);
        }
        __syncwarp();

        float oa[4][4];
#pragma unroll
        for (int j = 0; j < 4; j++)
#pragma unroll
            for (int t = 0; t < 4; t++) oa[j][t] = 0.f;

        const unsigned* Prow = Pme + rq * 36;
#pragma unroll
        for (int kc = 0; kc < 4; kc++) {
            const int base = kc * 8;
            unsigned a[4];
            a[0] = Prow[base + tq];
            a[1] = Prow[8 * 36 + base + tq];
            a[2] = Prow[base + tq + 4];
            a[3] = Prow[8 * 36 + base + tq + 4];
#pragma unroll
            for (int jn = 0; jn < 4; jn++) {
                unsigned b[2];
                const unsigned* Vr = Vt + (jn * 8 + rq) * 36 + base + tq;
                b[0] = Vr[0];
                b[1] = Vr[4];
                mma_bf16(oa[jn], a, b);
            }
        }

        const int l0 = wbase + (n0 >> 6) * 4096 + ((n0 >> 3) & 7) * 64 + (n0 & 7);
        const int l1 = wbase + (n1 >> 6) * 4096 + ((n1 >> 3) & 7) * 64 + (n1 & 7);
        __nv_bfloat16* o0 = o + (size_t)l0 * C + head * HD + tq * 2;
        __nv_bfloat16* o1 = o + (size_t)l1 * C + head * HD + tq * 2;
#pragma unroll
        for (int jn = 0; jn < 4; jn++) {
            *(unsigned*)(o0 + jn * 8) = packbf(oa[jn][0], oa[jn][1]);
            *(unsigned*)(o1 + jn * 8) = packbf(oa[jn][2], oa[jn][3]);
        }
    }
}

// ---------------- depthwise 3x3x3 conv: z-pair tile + smem weights ---------
// 384 thr = channel pairs; tile 2z x 2y x 8x; weights staged once in smem.
#define DW_SMEM_BYTES (27 * 768 * 4)
__global__ void __launch_bounds__(384)
dwconv_kernel(const __nv_bfloat16* __restrict__ hid,
              const float* __restrict__ wgt, const float* __restrict__ bias,
              __nv_bfloat16* __restrict__ hdn)
{
    extern __shared__ float sw[];     // [27][768]
    const int tid = threadIdx.x;      // 0..383 -> channel pair
    for (int i = tid; i < 27 * 768; i += 384) sw[i] = wgt[i];
    __syncthreads();

    const int bid = blockIdx.x;       // 4096
    const int x0  = (bid & 7) * 8;
    const int y0  = ((bid >> 3) & 31) * 2;
    const int z0  = (bid >> 8) * 2;
    const int ch  = tid * 2;

    float2 acc[2][2][8];
#pragma unroll
    for (int zi = 0; zi < 2; zi++)
#pragma unroll
        for (int yi = 0; yi < 2; yi++)
#pragma unroll
            for (int xi = 0; xi < 8; xi++) acc[zi][yi][xi] = make_float2(0.f, 0.f);

#pragma unroll 1
    for (int p = 0; p < 4; p++) {            // planes z0-1 .. z0+2
        int zz = z0 - 1 + p;
        if (zz < 0 || zz >= DD) continue;
#pragma unroll
        for (int r = 0; r < 4; r++) {        // rows y0-1 .. y0+2
            int yy = y0 - 1 + r;
            if (yy < 0 || yy >= HHH) continue;
            const __nv_bfloat16* base =
                hid + ((size_t)(zz * HHH + yy) * WWW) * HID + ch;
            float2 hv[10];
#pragma unroll
            for (int i = 0; i < 10; i++) {
                int xx = x0 - 1 + i;
                hv[i] = (xx >= 0 && xx < WWW) ? ldbf2(base + (size_t)xx * HID)
                                              : make_float2(0.f, 0.f);
            }
#pragma unroll
            for (int zi = 0; zi < 2; zi++) {
                int kd = p - zi;
                if (kd < 0 || kd > 2) continue;
#pragma unroll
                for (int yi = 0; yi < 2; yi++) {
                    int kh = r - yi;
                    if (kh < 0 || kh > 2) continue;
#pragma unroll
                    for (int kw = 0; kw < 3; kw++) {
                        float2 wv = *(const float2*)&sw[((kd * 3 + kh) * 3 + kw) * 768 + ch];
#pragma unroll
                        for (int xi = 0; xi < 8; xi++) {
                            acc[zi][yi][xi].x += hv[xi + kw].x * wv.x;
                            acc[zi][yi][xi].y += hv[xi + kw].y * wv.y;
                        }
                    }
                }
            }
        }
    }

    float2 bv = *(const float2*)&bias[ch];
#pragma unroll
    for (int zi = 0; zi < 2; zi++) {
#pragma unroll
        for (int yi = 0; yi < 2; yi++) {
#pragma unroll
            for (int xi = 0; xi < 8; xi++) {
                size_t idx = ((size_t)(((z0 + zi) * HHH + y0 + yi) * WWW + x0 + xi)) * HID + ch;
                float2 h0 = ldbf2(hid + idx);
                *(unsigned*)(hdn + idx) =
                    packbf(h0.x + gelu_f(acc[zi][yi][xi].x + bv.x),
                           h0.y + gelu_f(acc[zi][yi][xi].y + bv.y));
            }
        }
    }
}

// ---------------- launch ----------------------------------------------------
static void* sym_addr(const void* sym) {
    void* p = nullptr;
    cudaGetSymbolAddress(&p, sym);
    return p;
}

extern "C" void kernel_launch(void* const* d_in, const int* in_sizes, int n_in,
                              void* d_out, int out_size)
{
    const float* x    = (const float*)d_in[0];
    const float* n1g  = (const float*)d_in[1];
    const float* n1b  = (const float*)d_in[2];
    const float* q_w  = (const float*)d_in[3];
    const float* q_b  = (const float*)d_in[4];
    const float* kv_w = (const float*)d_in[5];
    const float* kv_b = (const float*)d_in[6];
    const float* btab = (const float*)d_in[7];
    const float* p_w  = (const float*)d_in[8];
    const float* p_b  = (const float*)d_in[9];
    const float* n2g  = (const float*)d_in[10];
    const float* n2b  = (const float*)d_in[11];
    const float* f1w  = (const float*)d_in[12];
    const float* f1b  = (const float*)d_in[13];
    const float* dww  = (const float*)d_in[14];
    const float* dwb  = (const float*)d_in[15];
    const float* f2w  = (const float*)d_in[16];
    const float* f2b  = (const float*)d_in[17];
    float* out = (float*)d_out;

    __nv_bfloat16* xnb  = (__nv_bfloat16*)sym_addr(g_xnb);
    __nv_bfloat16* qb_  = (__nv_bfloat16*)sym_addr(g_qb);
    __nv_bfloat16* kb_  = (__nv_bfloat16*)sym_addr(g_kb);
    __nv_bfloat16* vb_  = (__nv_bfloat16*)sym_addr(g_vb2);
    __nv_bfloat16* ob   = (__nv_bfloat16*)sym_addr(g_ob);
    float*         x1   = (float*)sym_addr(g_x1);
    __nv_bfloat16* hidb = (__nv_bfloat16*)sym_addr(g_hidb);
    __nv_bfloat16* hdnb = (__nv_bfloat16*)sym_addr(g_hdnb);
    __nv_bfloat16* pwT  = (__nv_bfloat16*)sym_addr(g_pwT);
    __nv_bfloat16* f1wT = (__nv_bfloat16*)sym_addr(g_f1wT);
    __nv_bfloat16* f2wT = (__nv_bfloat16*)sym_addr(g_f2wT);

    const int attn_smem = ATTN_SMEM_WORDS * 4;
    cudaFuncSetAttribute(attn_mma_kernel,
                         cudaFuncAttributeMaxDynamicSharedMemorySize, attn_smem);
    cudaFuncSetAttribute(gemm_qkv,
                         cudaFuncAttributeMaxDynamicSharedMemorySize, QKV_SMEM_BYTES);
    cudaFuncSetAttribute(gemm192<1>,
                         cudaFuncAttributeMaxDynamicSharedMemorySize, G192_SMEM_BYTES);
    cudaFuncSetAttribute(gemm192<2>,
                         cudaFuncAttributeMaxDynamicSharedMemorySize, G192_SMEM_BYTES);
    cudaFuncSetAttribute(gemm192<3>,
                         cudaFuncAttributeMaxDynamicSharedMemorySize, G192_SMEM_BYTES);
    cudaFuncSetAttribute(dwconv_kernel,
                         cudaFuncAttributeMaxDynamicSharedMemorySize, DW_SMEM_BYTES);

    // 0) weight prep
    prep_kernel<<<(PREP_R3 + 255) / 256, 256>>>(q_w, q_b, kv_w, kv_b, p_w, f1w, f2w);
    // 1) LN1 -> bf16
    ln_kernel<<<L / 8, 256>>>(x, n1g, n1b, xnb);
    // 2) fused q + kv projection (single col-block: A read once)
    gemm_qkv<<<dim3(1, L / 128), 512, QKV_SMEM_BYTES>>>(xnb, qb_, kb_, vb_);
    // 3) windowed attention
    attn_mma_kernel<<<NWIN * NHD, 256, attn_smem>>>(qb_, kb_, vb_, btab, ob);
    // 4) proj + residual + fused LN2
    gemm192<3><<<dim3(1, L / 128), 512, G192_SMEM_BYTES>>>(
        ob, pwT, p_b, x, x1, xnb, n2g, n2b, C, C);
    // 5) hid = gelu(xn @ fc1_w + fc1_b)
    gemm192<2><<<dim3(HID / 192, L / 128), 512, G192_SMEM_BYTES>>>(
        xnb, f1wT, f1b, nullptr, nullptr, hidb, nullptr, nullptr, HID, C);
    // 6) hdn = hid + gelu(dwconv(hid) + dw_b)  [z-pair tile + smem weights]
    dwconv_kernel<<<(DD / 2) * (HHH / 2) * (WWW / 8), 384, DW_SMEM_BYTES>>>(
        hidb, dww, dwb, hdnb);
    // 7) out = x1 + hdn @ fc2_w + fc2_b
    gemm192<1><<<dim3(1, L / 128), 512, G192_SMEM_BYTES>>>(
        hdnb, f2wT, f2b, x1, out, nullptr, nullptr, nullptr, C, HID);
}

// round 12
// speedup vs baseline: 1.6532x; 1.6532x over previous
#include <cuda_runtime.h>
#include <cuda_bf16.h>
#include <math.h>

// ---------------- problem constants ----------------
#define L     131072
#define C     192
#define NHD   6
#define HD    32
#define NWIN  256
#define NP    64
#define HID   768
#define DD    32
#define HHH   64
#define WWW   64

// ---------------- scratch ----------------
__device__ __nv_bfloat16 g_xnb [L * C];
__device__ __nv_bfloat16 g_qb  [L * C];
__device__ __nv_bfloat16 g_kb  [NWIN * NHD * NP * HD];
__device__ __nv_bfloat16 g_vb2 [NWIN * NHD * NP * HD];
__device__ __nv_bfloat16 g_ob  [L * C];
__device__ float         g_x1  [L * C];
__device__ __nv_bfloat16 g_hidb[L * HID];
__device__ __nv_bfloat16 g_hdnb[L * HID];
__device__ __nv_bfloat16 g_qkvT[256 * C];
__device__ float         g_qkvb[256];
__device__ __nv_bfloat16 g_pwT [C * C];
__device__ __nv_bfloat16 g_f1wT[HID * C];
__device__ __nv_bfloat16 g_f2wT[C * HID];
__device__ __nv_bfloat16 g_dwwb[27 * HID];

__device__ __forceinline__ float gelu_f(float v) {
    return 0.5f * v * (1.0f + erff(v * 0.70710678118654752f));
}

__device__ __forceinline__ void mma_bf16(float* d, const unsigned* a, const unsigned* b) {
    asm volatile(
        "mma.sync.aligned.m16n8k16.row.col.f32.bf16.bf16.f32 "
        "{%0,%1,%2,%3},{%4,%5,%6,%7},{%8,%9},{%0,%1,%2,%3};"
        : "+f"(d[0]), "+f"(d[1]), "+f"(d[2]), "+f"(d[3])
        : "r"(a[0]), "r"(a[1]), "r"(a[2]), "r"(a[3]), "r"(b[0]), "r"(b[1]));
}

#define LDSM_X4(r0, r1, r2, r3, addr) \
    asm volatile("ldmatrix.sync.aligned.m8n8.x4.shared.b16 {%0,%1,%2,%3}, [%4];" \
                 : "=r"(r0), "=r"(r1), "=r"(r2), "=r"(r3) : "r"(addr))

#define CP16(dst_smem_u32, src_ptr) \
    asm volatile("cp.async.cg.shared.global [%0], [%1], 16;\n" \
                 :: "r"(dst_smem_u32), "l"(src_ptr))
#define CP_COMMIT() asm volatile("cp.async.commit_group;\n" ::: "memory")
#define CP_WAIT1()  asm volatile("cp.async.wait_group 1;\n" ::: "memory")

__device__ __forceinline__ float4 ldbf4(const __nv_bfloat16* p) {
    uint2 u = *(const uint2*)p;
    float2 a = __bfloat1622float2(*(__nv_bfloat162*)&u.x);
    float2 b = __bfloat1622float2(*(__nv_bfloat162*)&u.y);
    return make_float4(a.x, a.y, b.x, b.y);
}
__device__ __forceinline__ void stbf4(__nv_bfloat16* p, float4 v) {
    uint2 u;
    *(__nv_bfloat162*)&u.x = __floats2bfloat162_rn(v.x, v.y);
    *(__nv_bfloat162*)&u.y = __floats2bfloat162_rn(v.z, v.w);
    *(uint2*)p = u;
}
__device__ __forceinline__ unsigned packbf(float a, float b) {
    __nv_bfloat162 t = __floats2bfloat162_rn(a, b);
    return *(unsigned*)&t;
}

// ------------- prep ------------
#define PREP_R0 (256 * 192)
#define PREP_R1 (PREP_R0 + 192 * 192)
#define PREP_R2 (PREP_R1 + 768 * 192)
#define PREP_R3 (PREP_R2 + 192 * 768)
#define PREP_R4 (PREP_R3 + 27 * 768)
__global__ void prep_kernel(const float* __restrict__ q_w, const float* __restrict__ q_b,
                            const float* __restrict__ kv_w, const float* __restrict__ kv_b,
                            const float* __restrict__ p_w, const float* __restrict__ f1w,
                            const float* __restrict__ f2w, const float* __restrict__ dww)
{
    const float qscale = 0.17677669529663687f;
    int id = blockIdx.x * 256 + threadIdx.x;
    if (id < 256) {
        float b = 0.f;
        if (id < 192)      b = q_b[id] * qscale;
        else if (id < 240) b = kv_b[id - 192];
        g_qkvb[id] = b;
    }
    if (id < PREP_R0) {
        int n = id / 192, k = id % 192;
        float v = 0.f;
        if (n < 192)      v = q_w[k * 192 + n] * qscale;
        else if (n < 240) v = kv_w[k * 48 + (n - 192)];
        g_qkvT[n * 192 + k] = __float2bfloat16(v);
    } else if (id < PREP_R1) {
        int e = id - PREP_R0, n = e / 192, k = e % 192;
        g_pwT[n * 192 + k] = __float2bfloat16(p_w[k * 192 + n]);
    } else if (id < PREP_R2) {
        int e = id - PREP_R1, n = e / 192, k = e % 192;
        g_f1wT[n * 192 + k] = __float2bfloat16(f1w[k * 768 + n]);
    } else if (id < PREP_R3) {
        int e = id - PREP_R2, n = e / 768, k = e % 768;
        g_f2wT[n * 768 + k] = __float2bfloat16(f2w[k * 192 + n]);
    } else if (id < PREP_R4) {
        int e = id - PREP_R3;
        g_dwwb[e] = __float2bfloat16(dww[e]);
    }
}

// ---------------- LayerNorm (fp32 in, bf16 out) — LN1 only -----------------
__global__ void ln_kernel(const float* __restrict__ x, const float* __restrict__ g,
                          const float* __restrict__ b, __nv_bfloat16* __restrict__ y)
{
    int lane = threadIdx.x & 31;
    int wi   = threadIdx.x >> 5;
    int l    = blockIdx.x * 8 + wi;
    const float* row = x + (size_t)l * C;
    float v[6];
    float s = 0.f, ss = 0.f;
#pragma unroll
    for (int i = 0; i < 6; i++) {
        v[i] = row[lane + 32 * i];
        s  += v[i];
        ss += v[i] * v[i];
    }
#pragma unroll
    for (int off = 16; off > 0; off >>= 1) {
        s  += __shfl_xor_sync(0xffffffffu, s,  off);
        ss += __shfl_xor_sync(0xffffffffu, ss, off);
    }
    float mean = s * (1.0f / C);
    float var  = ss * (1.0f / C) - mean * mean;
    float inv  = rsqrtf(var + 1e-5f);
    __nv_bfloat16* yr = y + (size_t)l * C;
#pragma unroll
    for (int i = 0; i < 6; i++) {
        int c = lane + 32 * i;
        yr[c] = __float2bfloat16((v[i] - mean) * inv * g[c] + b[c]);
    }
}

// -------- fused q+kv GEMM: 128x64 block, 4 warps, ldmatrix, scatter epi ----
#define QKV_SMEM_BYTES ((3 * (128 * 20 + 64 * 20)) * 4)
__global__ void __launch_bounds__(128)
gemm_qkv(const __nv_bfloat16* __restrict__ A,
         __nv_bfloat16* __restrict__ qout, __nv_bfloat16* __restrict__ ko,
         __nv_bfloat16* __restrict__ vo)
{
    extern __shared__ unsigned gsm[];
    unsigned* As = gsm;
    unsigned* Bs = gsm + 3 * 128 * 20;
    const int K = 192;

    const int tid  = threadIdx.x;
    const int lane = tid & 31, warp = tid >> 5;
    const int wm = warp & 1, wn = warp >> 1;
    const int row0 = blockIdx.y * 128, col0 = blockIdx.x * 64;

    float acc[4][4][4];
#pragma unroll
    for (int i = 0; i < 4; i++)
#pragma unroll
        for (int j = 0; j < 4; j++)
#pragma unroll
            for (int t = 0; t < 4; t++) acc[i][j][t] = 0.f;

    const unsigned sA = (unsigned)__cvta_generic_to_shared(As);
    const unsigned sB = (unsigned)__cvta_generic_to_shared(Bs);
    const __nv_bfloat16* Wt = g_qkvT;

    auto load_tile = [&](int kt, int st) {
        unsigned aOff = sA + (unsigned)(st * 128 * 20) * 4;
#pragma unroll
        for (int i = 0; i < 4; i++) {
            int id = tid + i * 128;
            int r = id >> 2, wc = (id & 3) * 4;
            CP16(aOff + (unsigned)(r * 20 + wc) * 4,
                 A + (size_t)(row0 + r) * K + kt + wc * 2);
        }
        unsigned bOff = sB + (unsigned)(st * 64 * 20) * 4;
#pragma unroll
        for (int i = 0; i < 2; i++) {
            int id = tid + i * 128;
            int r = id >> 2, wc = (id & 3) * 4;
            CP16(bOff + (unsigned)(r * 20 + wc) * 4,
                 Wt + (size_t)(col0 + r) * K + kt + wc * 2);
        }
        CP_COMMIT();
    };

    load_tile(0, 0);
    load_tile(32, 1);

    const int a_row_sel = lane & 15;
    const int a_k_sel   = (lane >> 4) * 4;
    const int b_row_sel = (lane & 7) + (lane >> 4) * 8;
    const int b_k_sel   = ((lane >> 3) & 1) * 4;
    const int rb0 = wm * 64, cb0 = wn * 32;

    int st = 0;
    for (int t = 0; t < 6; t++) {
        CP_WAIT1();
        __syncthreads();
        if (t + 2 < 6) {
            int st2 = st + 2; if (st2 >= 3) st2 -= 3;
            load_tile((t + 2) << 5, st2);
        }
        const unsigned sAst = sA + (unsigned)(st * 128 * 20) * 4;
        const unsigned sBst = sB + (unsigned)(st * 64 * 20) * 4;
#pragma unroll
        for (int ks = 0; ks < 2; ks++) {
            const int koff = ks * 8;
            unsigned af[4][4], bf[4][2];
#pragma unroll
            for (int mi = 0; mi < 4; mi++) {
                unsigned addr = sAst +
                    (unsigned)(((rb0 + mi * 16 + a_row_sel) * 20 + a_k_sel + koff) * 4);
                LDSM_X4(af[mi][0], af[mi][1], af[mi][2], af[mi][3], addr);
            }
#pragma unroll
            for (int g = 0; g < 2; g++) {
                unsigned r0, r1, r2, r3;
                unsigned addr = sBst +
                    (unsigned)(((cb0 + g * 16 + b_row_sel) * 20 + b_k_sel + koff) * 4);
                LDSM_X4(r0, r1, r2, r3, addr);
                bf[g * 2 + 0][0] = r0; bf[g * 2 + 0][1] = r1;
                bf[g * 2 + 1][0] = r2; bf[g * 2 + 1][1] = r3;
            }
#pragma unroll
            for (int mi = 0; mi < 4; mi++)
#pragma unroll
                for (int ni = 0; ni < 4; ni++)
                    mma_bf16(acc[mi][ni], af[mi], bf[ni]);
        }
        if (++st == 3) st = 0;
    }

    const int rq = lane >> 2, tq = lane & 3;
    const int crow0 = row0 + wm * 64 + rq;
    const int ccol  = col0 + wn * 32 + tq * 2;
#pragma unroll
    for (int mi = 0; mi < 4; mi++) {
#pragma unroll
        for (int half = 0; half < 2; half++) {
            int row = crow0 + mi * 16 + half * 8;
#pragma unroll
            for (int ni = 0; ni < 4; ni++) {
                int col = ccol + ni * 8;
                float v0 = acc[mi][ni][half * 2 + 0] + g_qkvb[col];
                float v1 = acc[mi][ni][half * 2 + 1] + g_qkvb[col + 1];
                if (col < 192) {
                    *(unsigned*)(qout + (size_t)row * 192 + col) = packbf(v0, v1);
                } else if (col < 240) {
                    int j = col - 192, jg = j >> 2, tt = j & 3;
                    __nv_bfloat16* dst = (jg < 6) ? ko : vo;
                    int head = (jg < 6) ? jg : jg - 6;
                    int z = row >> 12, y = (row >> 6) & 63, xq = row & 63;
                    int win = ((z >> 3) << 6) | ((y >> 3) << 3) | (xq >> 3);
                    int m = (((z & 7) >> 1) << 4) | (((y & 7) >> 1) << 2) | ((xq & 7) >> 1);
                    int sub = ((z & 1) << 2) | ((y & 1) << 1) | (xq & 1);
                    *(unsigned*)&dst[(((size_t)(win * 6 + head)) * 64 + m) * 32 + sub * 4 + tt] =
                        packbf(v0, v1);
                }
            }
        }
    }
}

// -------- wide GEMM 128x192, 512 thr; EPI: 1=+res fp32, 2=gelu bf16,
//          3 = +res -> x1 fp32 AND fused LayerNorm -> bf16 xout --------------
#define G192_SMEM_BYTES ((3 * (128 * 20 + 192 * 20)) * 4)
template <int EPI>
__global__ void __launch_bounds__(512)
gemm192(const __nv_bfloat16* __restrict__ A, const __nv_bfloat16* __restrict__ Wt,
        const float* __restrict__ bias, const float* __restrict__ res,
        float* __restrict__ Cf, __nv_bfloat16* __restrict__ Cb,
        const float* __restrict__ lng, const float* __restrict__ lnb,
        int N, int K)
{
    extern __shared__ unsigned gsm[];
    unsigned* As = gsm;
    unsigned* Bs = gsm + 3 * 128 * 20;

    const int tid  = threadIdx.x;
    const int lane = tid & 31, warp = tid >> 5;
    const int wm = warp & 3, wn = warp >> 2;
    const int row0 = blockIdx.y * 128, col0 = blockIdx.x * 192;

    float acc[2][6][4];
#pragma unroll
    for (int i = 0; i < 2; i++)
#pragma unroll
        for (int j = 0; j < 6; j++)
#pragma unroll
            for (int t = 0; t < 4; t++) acc[i][j][t] = 0.f;

    const unsigned sA = (unsigned)__cvta_generic_to_shared(As);
    const unsigned sB = (unsigned)__cvta_generic_to_shared(Bs);
    const int ntiles = K >> 5;

    auto load_tile = [&](int kt, int st) {
        unsigned aOff = sA + (unsigned)(st * 128 * 20) * 4;
        {
            int r = tid >> 2, wc = (tid & 3) * 4;
            CP16(aOff + (unsigned)(r * 20 + wc) * 4,
                 A + (size_t)(row0 + r) * K + kt + wc * 2);
        }
        unsigned bOff = sB + (unsigned)(st * 192 * 20) * 4;
        {
            int r = tid >> 2, wc = (tid & 3) * 4;
            CP16(bOff + (unsigned)(r * 20 + wc) * 4,
                 Wt + (size_t)(col0 + r) * K + kt + wc * 2);
            if (tid < 256) {
                int id = tid + 512;
                int r2 = id >> 2, wc2 = (id & 3) * 4;
                CP16(bOff + (unsigned)(r2 * 20 + wc2) * 4,
                     Wt + (size_t)(col0 + r2) * K + kt + wc2 * 2);
            }
        }
        CP_COMMIT();
    };

    load_tile(0, 0);
    load_tile(32, 1);

    const int a_row_sel = lane & 15;
    const int a_k_sel   = (lane >> 4) * 4;
    const int b_row_sel = (lane & 7) + (lane >> 4) * 8;
    const int b_k_sel   = ((lane >> 3) & 1) * 4;
    const int rb0 = wm * 32, cb0 = wn * 48;

    int st = 0;
    for (int t = 0; t < ntiles; t++) {
        CP_WAIT1();
        __syncthreads();
        if (t + 2 < ntiles) {
            int st2 = st + 2; if (st2 >= 3) st2 -= 3;
            load_tile((t + 2) << 5, st2);
        }
        const unsigned sAst = sA + (unsigned)(st * 128 * 20) * 4;
        const unsigned sBst = sB + (unsigned)(st * 192 * 20) * 4;
#pragma unroll
        for (int ks = 0; ks < 2; ks++) {
            const int koff = ks * 8;
            unsigned af[2][4], bf[6][2];
#pragma unroll
            for (int mi = 0; mi < 2; mi++) {
                unsigned addr = sAst +
                    (unsigned)(((rb0 + mi * 16 + a_row_sel) * 20 + a_k_sel + koff) * 4);
                LDSM_X4(af[mi][0], af[mi][1], af[mi][2], af[mi][3], addr);
            }
#pragma unroll
            for (int g = 0; g < 3; g++) {
                unsigned r0, r1, r2, r3;
                unsigned addr = sBst +
                    (unsigned)(((cb0 + g * 16 + b_row_sel) * 20 + b_k_sel + koff) * 4);
                LDSM_X4(r0, r1, r2, r3, addr);
                bf[g * 2 + 0][0] = r0; bf[g * 2 + 0][1] = r1;
                bf[g * 2 + 1][0] = r2; bf[g * 2 + 1][1] = r3;
            }
#pragma unroll
            for (int mi = 0; mi < 2; mi++)
#pragma unroll
                for (int ni = 0; ni < 6; ni++)
                    mma_bf16(acc[mi][ni], af[mi], bf[ni]);
        }
        if (++st == 3) st = 0;
    }

    const int rq = lane >> 2, tq = lane & 3;
    const int crow0 = row0 + wm * 32 + rq;
    const int ccol  = col0 + wn * 48 + tq * 2;

    if (EPI == 3) {
        __syncthreads();
        float* st_s  = (float*)gsm;
        float* st_ss = (float*)gsm + 512;
#pragma unroll
        for (int mi = 0; mi < 2; mi++)
#pragma unroll
            for (int half = 0; half < 2; half++) {
                int row = crow0 + mi * 16 + half * 8;
                float s = 0.f, ss = 0.f;
#pragma unroll
                for (int ni = 0; ni < 6; ni++) {
                    int col = ccol + ni * 8;
                    float2 rv = *(const float2*)(res + (size_t)row * 192 + col);
                    float v0 = acc[mi][ni][half * 2 + 0] + bias[col]     + rv.x;
                    float v1 = acc[mi][ni][half * 2 + 1] + bias[col + 1] + rv.y;
                    acc[mi][ni][half * 2 + 0] = v0;
                    acc[mi][ni][half * 2 + 1] = v1;
                    s += v0 + v1; ss += v0 * v0 + v1 * v1;
                }
                s  += __shfl_xor_sync(0xffffffffu, s, 1);
                s  += __shfl_xor_sync(0xffffffffu, s, 2);
                ss += __shfl_xor_sync(0xffffffffu, ss, 1);
                ss += __shfl_xor_sync(0xffffffffu, ss, 2);
                if (tq == 0) {
                    int rowl = wm * 32 + mi * 16 + half * 8 + rq;
                    st_s [rowl * 4 + wn] = s;
                    st_ss[rowl * 4 + wn] = ss;
                }
            }
        __syncthreads();
#pragma unroll
        for (int mi = 0; mi < 2; mi++)
#pragma unroll
            for (int half = 0; half < 2; half++) {
                int rowl = wm * 32 + mi * 16 + half * 8 + rq;
                int row  = row0 + rowl;
                float S  = st_s[rowl*4] + st_s[rowl*4+1] + st_s[rowl*4+2] + st_s[rowl*4+3];
                float SS = st_ss[rowl*4] + st_ss[rowl*4+1] + st_ss[rowl*4+2] + st_ss[rowl*4+3];
                float mean = S * (1.0f / 192.0f);
                float var  = SS * (1.0f / 192.0f) - mean * mean;
                float inv  = rsqrtf(var + 1e-5f);
#pragma unroll
                for (int ni = 0; ni < 6; ni++) {
                    int col = ccol + ni * 8;
                    float v0 = acc[mi][ni][half * 2 + 0];
                    float v1 = acc[mi][ni][half * 2 + 1];
                    *(float2*)(Cf + (size_t)row * 192 + col) = make_float2(v0, v1);
                    float n0 = (v0 - mean) * inv * lng[col]     + lnb[col];
                    float n1 = (v1 - mean) * inv * lng[col + 1] + lnb[col + 1];
                    *(unsigned*)(Cb + (size_t)row * 192 + col) = packbf(n0, n1);
                }
            }
        return;
    }

#pragma unroll
    for (int mi = 0; mi < 2; mi++) {
#pragma unroll
        for (int half = 0; half < 2; half++) {
            int row = crow0 + mi * 16 + half * 8;
#pragma unroll
            for (int ni = 0; ni < 6; ni++) {
                int col = ccol + ni * 8;
                float v0 = acc[mi][ni][half * 2 + 0] + bias[col];
                float v1 = acc[mi][ni][half * 2 + 1] + bias[col + 1];
                if (EPI == 1) {
                    float2 rv = *(const float2*)(res + (size_t)row * N + col);
                    *(float2*)(Cf + (size_t)row * N + col) =
                        make_float2(v0 + rv.x, v1 + rv.y);
                } else {
                    *(unsigned*)(Cb + (size_t)row * N + col) =
                        packbf(gelu_f(v0), gelu_f(v1));
                }
            }
        }
    }
}

// ---------------- attention: full bf16, m16n8k16 ----------------
#define ATTN_SMEM_WORDS (64*20 + 32*36 + 128*20 + 8*16*36 + 343)
__global__ void __launch_bounds__(256)
attn_mma_kernel(const __nv_bfloat16* __restrict__ q, const __nv_bfloat16* __restrict__ kbuf,
                const __nv_bfloat16* __restrict__ vbuf, const float* __restrict__ btab,
                __nv_bfloat16* __restrict__ o)
{
    extern __shared__ unsigned sm[];
    unsigned* Ks = sm;
    unsigned* Vt = Ks + 64 * 20;
    unsigned* Qs = Vt + 32 * 36;
    unsigned* Pw = Qs + 128 * 20;
    float*    bt = (float*)(Pw + 8 * 16 * 36);

    const int win  = blockIdx.x / NHD;
    const int head = blockIdx.x % NHD;
    const int tid = threadIdx.x, lane = tid & 31, w = tid >> 5;
    const int rq = lane >> 2, tq = lane & 3;

    const __nv_bfloat16* kb = kbuf + (size_t)(win * NHD + head) * NP * HD;
    const __nv_bfloat16* vb = vbuf + (size_t)(win * NHD + head) * NP * HD;
    for (int i = tid; i < 64 * 16; i += 256) {
        int m = i >> 4, wp = i & 15;
        Ks[m * 20 + wp] = ((const unsigned*)kb)[i];
    }
    for (int i = tid; i < 32 * 32; i += 256) {
        int c = i >> 5, mp = i & 31;
        Vt[c * 36 + mp] = packbf(__bfloat162float(vb[(2 * mp) * 32 + c]),
                                 __bfloat162float(vb[(2 * mp + 1) * 32 + c]));
    }
    for (int i = tid; i < 343; i += 256) bt[i] = btab[i * NHD + head];

    const int wz = win >> 6, wy = (win >> 3) & 7, wx = win & 7;
    const int wbase = wz * 32768 + wy * 512 + wx * 8;
    unsigned* Pme = Pw + w * 16 * 36;

#pragma unroll 1
    for (int p = 0; p < 4; p++) {
        __syncthreads();
#pragma unroll
        for (int i = 0; i < 2; i++) {
            int idx = tid + i * 256;
            int r = idx >> 2, wc = (idx & 3) * 4;
            int n = p * 128 + r;
            int l = wbase + (n >> 6) * 4096 + ((n >> 3) & 7) * 64 + (n & 7);
            uint4 v4 = *(const uint4*)(q + (size_t)l * C + head * HD + wc * 2);
            *(uint4*)&Qs[r * 20 + wc] = v4;
        }
        __syncthreads();

        float s[8][4];
#pragma unroll
        for (int j = 0; j < 8; j++)
#pragma unroll
            for (int t = 0; t < 4; t++) s[j][t] = 0.f;

        const unsigned* Qrow = Qs + (w * 16 + rq) * 20;
#pragma unroll
        for (int kc = 0; kc < 2; kc++) {
            const int kw = kc * 8;
            unsigned a[4];
            a[0] = Qrow[kw + tq];
            a[1] = Qrow[8 * 20 + kw + tq];
            a[2] = Qrow[kw + tq + 4];
            a[3] = Qrow[8 * 20 + kw + tq + 4];
#pragma unroll
            for (int j = 0; j < 8; j++) {
                unsigned b[2];
                const unsigned* Kr = Ks + (j * 8 + rq) * 20 + kw + tq;
                b[0] = Kr[0];
                b[1] = Kr[4];
                mma_bf16(s[j], a, b);
            }
        }

        const int n0 = p * 128 + w * 16 + rq;
        const int n1 = n0 + 8;
        int qb0, qb1;
        {
            int zz = n0 >> 6, yy = (n0 >> 3) & 7, xx = n0 & 7;
            qb0 = ((zz >> 1) + 3) * 49 + ((yy >> 1) + 3) * 7 + (xx >> 1) + 3;
            zz = n1 >> 6; yy = (n1 >> 3) & 7; xx = n1 & 7;
            qb1 = ((zz >> 1) + 3) * 49 + ((yy >> 1) + 3) * 7 + (xx >> 1) + 3;
        }
        float mx0 = -1e30f, mx1 = -1e30f;
#pragma unroll
        for (int j = 0; j < 8; j++) {
#pragma unroll
            for (int s2 = 0; s2 < 2; s2++) {
                int m = j * 8 + tq * 2 + s2;
                int koff = (m >> 4) * 49 + ((m >> 2) & 3) * 7 + (m & 3);
                s[j][s2]     += bt[qb0 - koff];
                s[j][2 + s2] += bt[qb1 - koff];
                mx0 = fmaxf(mx0, s[j][s2]);
                mx1 = fmaxf(mx1, s[j][2 + s2]);
            }
        }
        mx0 = fmaxf(mx0, __shfl_xor_sync(0xffffffffu, mx0, 1));
        mx0 = fmaxf(mx0, __shfl_xor_sync(0xffffffffu, mx0, 2));
        mx1 = fmaxf(mx1, __shfl_xor_sync(0xffffffffu, mx1, 1));
        mx1 = fmaxf(mx1, __shfl_xor_sync(0xffffffffu, mx1, 2));
        float sum0 = 0.f, sum1 = 0.f;
#pragma unroll
        for (int j = 0; j < 8; j++) {
#pragma unroll
            for (int s2 = 0; s2 < 2; s2++) {
                s[j][s2]     = __expf(s[j][s2]     - mx0);
                s[j][2 + s2] = __expf(s[j][2 + s2] - mx1);
                sum0 += s[j][s2];
                sum1 += s[j][2 + s2];
            }
        }
        sum0 += __shfl_xor_sync(0xffffffffu, sum0, 1);
        sum0 += __shfl_xor_sync(0xffffffffu, sum0, 2);
        sum1 += __shfl_xor_sync(0xffffffffu, sum1, 1);
        sum1 += __shfl_xor_sync(0xffffffffu, sum1, 2);
        const float inv0 = 1.0f / sum0, inv1 = 1.0f / sum1;

#pragma unroll
        for (int j = 0; j < 8; j++) {
            Pme[rq * 36 + j * 4 + tq]       = packbf(s[j][0] * inv0, s[j][1] * inv0);
            Pme[(rq + 8) * 36 + j * 4 + tq] = packbf(s[j][2] * inv1, s[j][3] * inv1);
        }
        __syncwarp();

        float oa[4][4];
#pragma unroll
        for (int j = 0; j < 4; j++)
#pragma unroll
            for (int t = 0; t < 4; t++) oa[j][t] = 0.f;

        const unsigned* Prow = Pme + rq * 36;
#pragma unroll
        for (int kc = 0; kc < 4; kc++) {
            const int base = kc * 8;
            unsigned a[4];
            a[0] = Prow[base + tq];
            a[1] = Prow[8 * 36 + base + tq];
            a[2] = Prow[base + tq + 4];
            a[3] = Prow[8 * 36 + base + tq + 4];
#pragma unroll
            for (int jn = 0; jn < 4; jn++) {
                unsigned b[2];
                const unsigned* Vr = Vt + (jn * 8 + rq) * 36 + base + tq;
                b[0] = Vr[0];
                b[1] = Vr[4];
                mma_bf16(oa[jn], a, b);
            }
        }

        const int l0 = wbase + (n0 >> 6) * 4096 + ((n0 >> 3) & 7) * 64 + (n0 & 7);
        const int l1 = wbase + (n1 >> 6) * 4096 + ((n1 >> 3) & 7) * 64 + (n1 & 7);
        __nv_bfloat16* o0 = o + (size_t)l0 * C + head * HD + tq * 2;
        __nv_bfloat16* o1 = o + (size_t)l1 * C + head * HD + tq * 2;
#pragma unroll
        for (int jn = 0; jn < 4; jn++) {
            *(unsigned*)(o0 + jn * 8) = packbf(oa[jn][0], oa[jn][1]);
            *(unsigned*)(o1 + jn * 8) = packbf(oa[jn][2], oa[jn][3]);
        }
    }
}

// ---------------- depthwise 3x3x3 conv (bf16 io + bf16 weights) ------------
// round-10 shape: 192 thr = float4 channel groups, tile 2y x 8x.
__global__ void dwconv_kernel(const __nv_bfloat16* __restrict__ hid,
                              const float* __restrict__ bias,
                              __nv_bfloat16* __restrict__ hdn)
{
    const int c4  = threadIdx.x;
    const int bid = blockIdx.x;
    const int x0  = (bid & 7) * 8;
    const int y0  = ((bid >> 3) & 31) * 2;
    const int z   = bid >> 8;

    float4 acc[2][8];
#pragma unroll
    for (int yi = 0; yi < 2; yi++)
#pragma unroll
        for (int i = 0; i < 8; i++) acc[yi][i] = make_float4(0.f, 0.f, 0.f, 0.f);

    for (int kd = 0; kd < 3; kd++) {
        int zz = z + kd - 1;
        if (zz < 0 || zz >= DD) continue;
#pragma unroll
        for (int r = 0; r < 4; r++) {
            int yy = y0 - 1 + r;
            if (yy < 0 || yy >= HHH) continue;
            const __nv_bfloat16* base =
                hid + ((size_t)(zz * HHH + yy) * WWW) * HID + c4 * 4;
            float4 hv[10];
#pragma unroll
            for (int i = 0; i < 10; i++) {
                int xx = x0 - 1 + i;
                hv[i] = (xx >= 0 && xx < WWW) ? ldbf4(base + (size_t)xx * HID)
                                              : make_float4(0.f, 0.f, 0.f, 0.f);
            }
#pragma unroll
            for (int yi = 0; yi < 2; yi++) {
                int kh = r - yi;
                if (kh < 0 || kh > 2) continue;
#pragma unroll
                for (int kw = 0; kw < 3; kw++) {
                    float4 wv = ldbf4(g_dwwb + ((kd * 3 + kh) * 3 + kw) * HID + c4 * 4);
#pragma unroll
                    for (int xi = 0; xi < 8; xi++) {
                        acc[yi][xi].x += hv[xi + kw].x * wv.x;
                        acc[yi][xi].y += hv[xi + kw].y * wv.y;
                        acc[yi][xi].z += hv[xi + kw].z * wv.z;
                        acc[yi][xi].w += hv[xi + kw].w * wv.w;
                    }
                }
            }
        }
    }
    float4 bv = *(const float4*)(bias + c4 * 4);
#pragma unroll
    for (int yi = 0; yi < 2; yi++) {
#pragma unroll
        for (int xi = 0; xi < 8; xi++) {
            size_t idx = ((size_t)((z * HHH + y0 + yi) * WWW + x0 + xi)) * HID + c4 * 4;
            float4 h0 = ldbf4(hid + idx);
            float4 o;
            o.x = h0.x + gelu_f(acc[yi][xi].x + bv.x);
            o.y = h0.y + gelu_f(acc[yi][xi].y + bv.y);
            o.z = h0.z + gelu_f(acc[yi][xi].z + bv.z);
            o.w = h0.w + gelu_f(acc[yi][xi].w + bv.w);
            stbf4(hdn + idx, o);
        }
    }
}

// ---------------- launch ----------------------------------------------------
static void* sym_addr(const void* sym) {
    void* p = nullptr;
    cudaGetSymbolAddress(&p, sym);
    return p;
}

extern "C" void kernel_launch(void* const* d_in, const int* in_sizes, int n_in,
                              void* d_out, int out_size)
{
    const float* x    = (const float*)d_in[0];
    const float* n1g  = (const float*)d_in[1];
    const float* n1b  = (const float*)d_in[2];
    const float* q_w  = (const float*)d_in[3];
    const float* q_b  = (const float*)d_in[4];
    const float* kv_w = (const float*)d_in[5];
    const float* kv_b = (const float*)d_in[6];
    const float* btab = (const float*)d_in[7];
    const float* p_w  = (const float*)d_in[8];
    const float* p_b  = (const float*)d_in[9];
    const float* n2g  = (const float*)d_in[10];
    const float* n2b  = (const float*)d_in[11];
    const float* f1w  = (const float*)d_in[12];
    const float* f1b  = (const float*)d_in[13];
    const float* dww  = (const float*)d_in[14];
    const float* dwb  = (const float*)d_in[15];
    const float* f2w  = (const float*)d_in[16];
    const float* f2b  = (const float*)d_in[17];
    float* out = (float*)d_out;

    __nv_bfloat16* xnb  = (__nv_bfloat16*)sym_addr(g_xnb);
    __nv_bfloat16* qb_  = (__nv_bfloat16*)sym_addr(g_qb);
    __nv_bfloat16* kb_  = (__nv_bfloat16*)sym_addr(g_kb);
    __nv_bfloat16* vb_  = (__nv_bfloat16*)sym_addr(g_vb2);
    __nv_bfloat16* ob   = (__nv_bfloat16*)sym_addr(g_ob);
    float*         x1   = (float*)sym_addr(g_x1);
    __nv_bfloat16* hidb = (__nv_bfloat16*)sym_addr(g_hidb);
    __nv_bfloat16* hdnb = (__nv_bfloat16*)sym_addr(g_hdnb);
    __nv_bfloat16* pwT  = (__nv_bfloat16*)sym_addr(g_pwT);
    __nv_bfloat16* f1wT = (__nv_bfloat16*)sym_addr(g_f1wT);
    __nv_bfloat16* f2wT = (__nv_bfloat16*)sym_addr(g_f2wT);

    const int attn_smem = ATTN_SMEM_WORDS * 4;
    cudaFuncSetAttribute(attn_mma_kernel,
                         cudaFuncAttributeMaxDynamicSharedMemorySize, attn_smem);
    cudaFuncSetAttribute(gemm_qkv,
                         cudaFuncAttributeMaxDynamicSharedMemorySize, QKV_SMEM_BYTES);
    cudaFuncSetAttribute(gemm192<1>,
                         cudaFuncAttributeMaxDynamicSharedMemorySize, G192_SMEM_BYTES);
    cudaFuncSetAttribute(gemm192<2>,
                         cudaFuncAttributeMaxDynamicSharedMemorySize, G192_SMEM_BYTES);
    cudaFuncSetAttribute(gemm192<3>,
                         cudaFuncAttributeMaxDynamicSharedMemorySize, G192_SMEM_BYTES);

    // 0) weight prep (now includes bf16 depthwise weights)
    prep_kernel<<<(PREP_R4 + 255) / 256, 256>>>(q_w, q_b, kv_w, kv_b, p_w, f1w, f2w, dww);
    // 1) LN1 -> bf16
    ln_kernel<<<L / 8, 256>>>(x, n1g, n1b, xnb);
    // 2) fused q + kv projection (round-10 config: 4 col-blocks)
    gemm_qkv<<<dim3(4, L / 128), 128, QKV_SMEM_BYTES>>>(xnb, qb_, kb_, vb_);
    // 3) windowed attention
    attn_mma_kernel<<<NWIN * NHD, 256, attn_smem>>>(qb_, kb_, vb_, btab, ob);
    // 4) proj + residual + fused LN2
    gemm192<3><<<dim3(1, L / 128), 512, G192_SMEM_BYTES>>>(
        ob, pwT, p_b, x, x1, xnb, n2g, n2b, C, C);
    // 5) hid = gelu(xn @ fc1_w + fc1_b)
    gemm192<2><<<dim3(HID / 192, L / 128), 512, G192_SMEM_BYTES>>>(
        xnb, f1wT, f1b, nullptr, nullptr, hidb, nullptr, nullptr, HID, C);
    // 6) hdn = hid + gelu(dwconv(hid) + dw_b)  [round-10 shape, bf16 weights]
    dwconv_kernel<<<(DD * HHH * WWW) / 16, 192>>>(hidb, dwb, hdnb);
    // 7) out = x1 + hdn @ fc2_w + fc2_b
    gemm192<1><<<dim3(1, L / 128), 512, G192_SMEM_BYTES>>>(
        hdnb, f2wT, f2b, x1, out, nullptr, nullptr, nullptr, C, HID);
}

// round 13
// speedup vs baseline: 1.6934x; 1.0243x over previous
#include <cuda_runtime.h>
#include <cuda_bf16.h>
#include <math.h>

// ---------------- problem constants ----------------
#define L     131072
#define C     192
#define NHD   6
#define HD    32
#define NWIN  256
#define NP    64
#define HID   768
#define DD    32
#define HHH   64
#define WWW   64

// ---------------- scratch ----------------
__device__ __nv_bfloat16 g_xnb [L * C];
__device__ __nv_bfloat16 g_qb  [L * C];
__device__ __nv_bfloat16 g_kb  [NWIN * NHD * NP * HD];
__device__ __nv_bfloat16 g_vb2 [NWIN * NHD * NP * HD];
__device__ __nv_bfloat16 g_ob  [L * C];
__device__ float         g_x1  [L * C];
__device__ __nv_bfloat16 g_hidb[L * HID];
__device__ __nv_bfloat16 g_hdnb[L * HID];
__device__ __nv_bfloat16 g_qkvT[256 * C];
__device__ float         g_qkvb[256];
__device__ __nv_bfloat16 g_pwT [C * C];
__device__ __nv_bfloat16 g_f1wT[HID * C];
__device__ __nv_bfloat16 g_f2wT[C * HID];
__device__ __nv_bfloat16 g_dwwb[27 * HID];

__device__ __forceinline__ float gelu_f(float v) {
    return 0.5f * v * (1.0f + erff(v * 0.70710678118654752f));
}

__device__ __forceinline__ void mma_bf16(float* d, const unsigned* a, const unsigned* b) {
    asm volatile(
        "mma.sync.aligned.m16n8k16.row.col.f32.bf16.bf16.f32 "
        "{%0,%1,%2,%3},{%4,%5,%6,%7},{%8,%9},{%0,%1,%2,%3};"
        : "+f"(d[0]), "+f"(d[1]), "+f"(d[2]), "+f"(d[3])
        : "r"(a[0]), "r"(a[1]), "r"(a[2]), "r"(a[3]), "r"(b[0]), "r"(b[1]));
}

#define LDSM_X4(r0, r1, r2, r3, addr) \
    asm volatile("ldmatrix.sync.aligned.m8n8.x4.shared.b16 {%0,%1,%2,%3}, [%4];" \
                 : "=r"(r0), "=r"(r1), "=r"(r2), "=r"(r3) : "r"(addr))

#define CP16(dst_smem_u32, src_ptr) \
    asm volatile("cp.async.cg.shared.global [%0], [%1], 16;\n" \
                 :: "r"(dst_smem_u32), "l"(src_ptr))
#define CP_COMMIT() asm volatile("cp.async.commit_group;\n" ::: "memory")
#define CP_WAIT1()  asm volatile("cp.async.wait_group 1;\n" ::: "memory")
#define CP_WAIT0()  asm volatile("cp.async.wait_group 0;\n" ::: "memory")

__device__ __forceinline__ float4 ldbf4(const __nv_bfloat16* p) {
    uint2 u = *(const uint2*)p;
    float2 a = __bfloat1622float2(*(__nv_bfloat162*)&u.x);
    float2 b = __bfloat1622float2(*(__nv_bfloat162*)&u.y);
    return make_float4(a.x, a.y, b.x, b.y);
}
__device__ __forceinline__ void stbf4(__nv_bfloat16* p, float4 v) {
    uint2 u;
    *(__nv_bfloat162*)&u.x = __floats2bfloat162_rn(v.x, v.y);
    *(__nv_bfloat162*)&u.y = __floats2bfloat162_rn(v.z, v.w);
    *(uint2*)p = u;
}
__device__ __forceinline__ unsigned packbf(float a, float b) {
    __nv_bfloat162 t = __floats2bfloat162_rn(a, b);
    return *(unsigned*)&t;
}

// ------------- prep ------------
#define PREP_R0 (256 * 192)
#define PREP_R1 (PREP_R0 + 192 * 192)
#define PREP_R2 (PREP_R1 + 768 * 192)
#define PREP_R3 (PREP_R2 + 192 * 768)
#define PREP_R4 (PREP_R3 + 27 * 768)
__global__ void prep_kernel(const float* __restrict__ q_w, const float* __restrict__ q_b,
                            const float* __restrict__ kv_w, const float* __restrict__ kv_b,
                            const float* __restrict__ p_w, const float* __restrict__ f1w,
                            const float* __restrict__ f2w, const float* __restrict__ dww)
{
    const float qscale = 0.17677669529663687f;
    int id = blockIdx.x * 256 + threadIdx.x;
    if (id < 256) {
        float b = 0.f;
        if (id < 192)      b = q_b[id] * qscale;
        else if (id < 240) b = kv_b[id - 192];
        g_qkvb[id] = b;
    }
    if (id < PREP_R0) {
        int n = id / 192, k = id % 192;
        float v = 0.f;
        if (n < 192)      v = q_w[k * 192 + n] * qscale;
        else if (n < 240) v = kv_w[k * 48 + (n - 192)];
        g_qkvT[n * 192 + k] = __float2bfloat16(v);
    } else if (id < PREP_R1) {
        int e = id - PREP_R0, n = e / 192, k = e % 192;
        g_pwT[n * 192 + k] = __float2bfloat16(p_w[k * 192 + n]);
    } else if (id < PREP_R2) {
        int e = id - PREP_R1, n = e / 192, k = e % 192;
        g_f1wT[n * 192 + k] = __float2bfloat16(f1w[k * 768 + n]);
    } else if (id < PREP_R3) {
        int e = id - PREP_R2, n = e / 768, k = e % 768;
        g_f2wT[n * 768 + k] = __float2bfloat16(f2w[k * 192 + n]);
    } else if (id < PREP_R4) {
        int e = id - PREP_R3;
        g_dwwb[e] = __float2bfloat16(dww[e]);
    }
}

// ---------------- LayerNorm (fp32 in, bf16 out) — LN1 only -----------------
__global__ void ln_kernel(const float* __restrict__ x, const float* __restrict__ g,
                          const float* __restrict__ b, __nv_bfloat16* __restrict__ y)
{
    int lane = threadIdx.x & 31;
    int wi   = threadIdx.x >> 5;
    int l    = blockIdx.x * 8 + wi;
    const float* row = x + (size_t)l * C;
    float v[6];
    float s = 0.f, ss = 0.f;
#pragma unroll
    for (int i = 0; i < 6; i++) {
        v[i] = row[lane + 32 * i];
        s  += v[i];
        ss += v[i] * v[i];
    }
#pragma unroll
    for (int off = 16; off > 0; off >>= 1) {
        s  += __shfl_xor_sync(0xffffffffu, s,  off);
        ss += __shfl_xor_sync(0xffffffffu, ss, off);
    }
    float mean = s * (1.0f / C);
    float var  = ss * (1.0f / C) - mean * mean;
    float inv  = rsqrtf(var + 1e-5f);
    __nv_bfloat16* yr = y + (size_t)l * C;
#pragma unroll
    for (int i = 0; i < 6; i++) {
        int c = lane + 32 * i;
        yr[c] = __float2bfloat16((v[i] - mean) * inv * g[c] + b[c]);
    }
}

// -------- fused q+kv GEMM: 128x64 block, 4 warps, ldmatrix, scatter epi ----
#define QKV_SMEM_BYTES ((3 * (128 * 20 + 64 * 20)) * 4)
__global__ void __launch_bounds__(128)
gemm_qkv(const __nv_bfloat16* __restrict__ A,
         __nv_bfloat16* __restrict__ qout, __nv_bfloat16* __restrict__ ko,
         __nv_bfloat16* __restrict__ vo)
{
    extern __shared__ unsigned gsm[];
    unsigned* As = gsm;
    unsigned* Bs = gsm + 3 * 128 * 20;
    const int K = 192;

    const int tid  = threadIdx.x;
    const int lane = tid & 31, warp = tid >> 5;
    const int wm = warp & 1, wn = warp >> 1;
    const int row0 = blockIdx.y * 128, col0 = blockIdx.x * 64;

    float acc[4][4][4];
#pragma unroll
    for (int i = 0; i < 4; i++)
#pragma unroll
        for (int j = 0; j < 4; j++)
#pragma unroll
            for (int t = 0; t < 4; t++) acc[i][j][t] = 0.f;

    const unsigned sA = (unsigned)__cvta_generic_to_shared(As);
    const unsigned sB = (unsigned)__cvta_generic_to_shared(Bs);
    const __nv_bfloat16* Wt = g_qkvT;

    auto load_tile = [&](int kt, int st) {
        unsigned aOff = sA + (unsigned)(st * 128 * 20) * 4;
#pragma unroll
        for (int i = 0; i < 4; i++) {
            int id = tid + i * 128;
            int r = id >> 2, wc = (id & 3) * 4;
            CP16(aOff + (unsigned)(r * 20 + wc) * 4,
                 A + (size_t)(row0 + r) * K + kt + wc * 2);
        }
        unsigned bOff = sB + (unsigned)(st * 64 * 20) * 4;
#pragma unroll
        for (int i = 0; i < 2; i++) {
            int id = tid + i * 128;
            int r = id >> 2, wc = (id & 3) * 4;
            CP16(bOff + (unsigned)(r * 20 + wc) * 4,
                 Wt + (size_t)(col0 + r) * K + kt + wc * 2);
        }
        CP_COMMIT();
    };

    load_tile(0, 0);
    load_tile(32, 1);

    const int a_row_sel = lane & 15;
    const int a_k_sel   = (lane >> 4) * 4;
    const int b_row_sel = (lane & 7) + (lane >> 4) * 8;
    const int b_k_sel   = ((lane >> 3) & 1) * 4;
    const int rb0 = wm * 64, cb0 = wn * 32;

    int st = 0;
    for (int t = 0; t < 6; t++) {
        if (t + 1 < 6) CP_WAIT1(); else CP_WAIT0();
        __syncthreads();
        if (t + 2 < 6) {
            int st2 = st + 2; if (st2 >= 3) st2 -= 3;
            load_tile((t + 2) << 5, st2);
        }
        const unsigned sAst = sA + (unsigned)(st * 128 * 20) * 4;
        const unsigned sBst = sB + (unsigned)(st * 64 * 20) * 4;
#pragma unroll
        for (int ks = 0; ks < 2; ks++) {
            const int koff = ks * 8;
            unsigned af[4][4], bf[4][2];
#pragma unroll
            for (int mi = 0; mi < 4; mi++) {
                unsigned addr = sAst +
                    (unsigned)(((rb0 + mi * 16 + a_row_sel) * 20 + a_k_sel + koff) * 4);
                LDSM_X4(af[mi][0], af[mi][1], af[mi][2], af[mi][3], addr);
            }
#pragma unroll
            for (int g = 0; g < 2; g++) {
                unsigned r0, r1, r2, r3;
                unsigned addr = sBst +
                    (unsigned)(((cb0 + g * 16 + b_row_sel) * 20 + b_k_sel + koff) * 4);
                LDSM_X4(r0, r1, r2, r3, addr);
                bf[g * 2 + 0][0] = r0; bf[g * 2 + 0][1] = r1;
                bf[g * 2 + 1][0] = r2; bf[g * 2 + 1][1] = r3;
            }
#pragma unroll
            for (int mi = 0; mi < 4; mi++)
#pragma unroll
                for (int ni = 0; ni < 4; ni++)
                    mma_bf16(acc[mi][ni], af[mi], bf[ni]);
        }
        if (++st == 3) st = 0;
    }

    const int rq = lane >> 2, tq = lane & 3;
    const int crow0 = row0 + wm * 64 + rq;
    const int ccol  = col0 + wn * 32 + tq * 2;
#pragma unroll
    for (int mi = 0; mi < 4; mi++) {
#pragma unroll
        for (int half = 0; half < 2; half++) {
            int row = crow0 + mi * 16 + half * 8;
#pragma unroll
            for (int ni = 0; ni < 4; ni++) {
                int col = ccol + ni * 8;
                float v0 = acc[mi][ni][half * 2 + 0] + g_qkvb[col];
                float v1 = acc[mi][ni][half * 2 + 1] + g_qkvb[col + 1];
                if (col < 192) {
                    *(unsigned*)(qout + (size_t)row * 192 + col) = packbf(v0, v1);
                } else if (col < 240) {
                    int j = col - 192, jg = j >> 2, tt = j & 3;
                    __nv_bfloat16* dst = (jg < 6) ? ko : vo;
                    int head = (jg < 6) ? jg : jg - 6;
                    int z = row >> 12, y = (row >> 6) & 63, xq = row & 63;
                    int win = ((z >> 3) << 6) | ((y >> 3) << 3) | (xq >> 3);
                    int m = (((z & 7) >> 1) << 4) | (((y & 7) >> 1) << 2) | ((xq & 7) >> 1);
                    int sub = ((z & 1) << 2) | ((y & 1) << 1) | (xq & 1);
                    *(unsigned*)&dst[(((size_t)(win * 6 + head)) * 64 + m) * 32 + sub * 4 + tt] =
                        packbf(v0, v1);
                }
            }
        }
    }
}

// -------- wide GEMM 128x192, 512 thr; EPI: 1=+res fp32, 3=+res+LN fused ----
#define G192_SMEM_BYTES ((3 * (128 * 20 + 192 * 20)) * 4)
template <int EPI>
__global__ void __launch_bounds__(512)
gemm192(const __nv_bfloat16* __restrict__ A, const __nv_bfloat16* __restrict__ Wt,
        const float* __restrict__ bias, const float* __restrict__ res,
        float* __restrict__ Cf, __nv_bfloat16* __restrict__ Cb,
        const float* __restrict__ lng, const float* __restrict__ lnb,
        int N, int K)
{
    extern __shared__ unsigned gsm[];
    unsigned* As = gsm;
    unsigned* Bs = gsm + 3 * 128 * 20;

    const int tid  = threadIdx.x;
    const int lane = tid & 31, warp = tid >> 5;
    const int wm = warp & 3, wn = warp >> 2;
    const int row0 = blockIdx.y * 128, col0 = blockIdx.x * 192;

    float acc[2][6][4];
#pragma unroll
    for (int i = 0; i < 2; i++)
#pragma unroll
        for (int j = 0; j < 6; j++)
#pragma unroll
            for (int t = 0; t < 4; t++) acc[i][j][t] = 0.f;

    const unsigned sA = (unsigned)__cvta_generic_to_shared(As);
    const unsigned sB = (unsigned)__cvta_generic_to_shared(Bs);
    const int ntiles = K >> 5;

    auto load_tile = [&](int kt, int st) {
        unsigned aOff = sA + (unsigned)(st * 128 * 20) * 4;
        {
            int r = tid >> 2, wc = (tid & 3) * 4;
            CP16(aOff + (unsigned)(r * 20 + wc) * 4,
                 A + (size_t)(row0 + r) * K + kt + wc * 2);
        }
        unsigned bOff = sB + (unsigned)(st * 192 * 20) * 4;
        {
            int r = tid >> 2, wc = (tid & 3) * 4;
            CP16(bOff + (unsigned)(r * 20 + wc) * 4,
                 Wt + (size_t)(col0 + r) * K + kt + wc * 2);
            if (tid < 256) {
                int id = tid + 512;
                int r2 = id >> 2, wc2 = (id & 3) * 4;
                CP16(bOff + (unsigned)(r2 * 20 + wc2) * 4,
                     Wt + (size_t)(col0 + r2) * K + kt + wc2 * 2);
            }
        }
        CP_COMMIT();
    };

    load_tile(0, 0);
    load_tile(32, 1);

    const int a_row_sel = lane & 15;
    const int a_k_sel   = (lane >> 4) * 4;
    const int b_row_sel = (lane & 7) + (lane >> 4) * 8;
    const int b_k_sel   = ((lane >> 3) & 1) * 4;
    const int rb0 = wm * 32, cb0 = wn * 48;

    int st = 0;
    for (int t = 0; t < ntiles; t++) {
        if (t + 1 < ntiles) CP_WAIT1(); else CP_WAIT0();
        __syncthreads();
        if (t + 2 < ntiles) {
            int st2 = st + 2; if (st2 >= 3) st2 -= 3;
            load_tile((t + 2) << 5, st2);
        }
        const unsigned sAst = sA + (unsigned)(st * 128 * 20) * 4;
        const unsigned sBst = sB + (unsigned)(st * 192 * 20) * 4;
#pragma unroll
        for (int ks = 0; ks < 2; ks++) {
            const int koff = ks * 8;
            unsigned af[2][4], bf[6][2];
#pragma unroll
            for (int mi = 0; mi < 2; mi++) {
                unsigned addr = sAst +
                    (unsigned)(((rb0 + mi * 16 + a_row_sel) * 20 + a_k_sel + koff) * 4);
                LDSM_X4(af[mi][0], af[mi][1], af[mi][2], af[mi][3], addr);
            }
#pragma unroll
            for (int g = 0; g < 3; g++) {
                unsigned r0, r1, r2, r3;
                unsigned addr = sBst +
                    (unsigned)(((cb0 + g * 16 + b_row_sel) * 20 + b_k_sel + koff) * 4);
                LDSM_X4(r0, r1, r2, r3, addr);
                bf[g * 2 + 0][0] = r0; bf[g * 2 + 0][1] = r1;
                bf[g * 2 + 1][0] = r2; bf[g * 2 + 1][1] = r3;
            }
#pragma unroll
            for (int mi = 0; mi < 2; mi++)
#pragma unroll
                for (int ni = 0; ni < 6; ni++)
                    mma_bf16(acc[mi][ni], af[mi], bf[ni]);
        }
        if (++st == 3) st = 0;
    }

    const int rq = lane >> 2, tq = lane & 3;
    const int crow0 = row0 + wm * 32 + rq;
    const int ccol  = col0 + wn * 48 + tq * 2;

    if (EPI == 3) {
        __syncthreads();
        float* st_s  = (float*)gsm;
        float* st_ss = (float*)gsm + 512;
#pragma unroll
        for (int mi = 0; mi < 2; mi++)
#pragma unroll
            for (int half = 0; half < 2; half++) {
                int row = crow0 + mi * 16 + half * 8;
                float s = 0.f, ss = 0.f;
#pragma unroll
                for (int ni = 0; ni < 6; ni++) {
                    int col = ccol + ni * 8;
                    float2 rv = *(const float2*)(res + (size_t)row * 192 + col);
                    float v0 = acc[mi][ni][half * 2 + 0] + bias[col]     + rv.x;
                    float v1 = acc[mi][ni][half * 2 + 1] + bias[col + 1] + rv.y;
                    acc[mi][ni][half * 2 + 0] = v0;
                    acc[mi][ni][half * 2 + 1] = v1;
                    s += v0 + v1; ss += v0 * v0 + v1 * v1;
                }
                s  += __shfl_xor_sync(0xffffffffu, s, 1);
                s  += __shfl_xor_sync(0xffffffffu, s, 2);
                ss += __shfl_xor_sync(0xffffffffu, ss, 1);
                ss += __shfl_xor_sync(0xffffffffu, ss, 2);
                if (tq == 0) {
                    int rowl = wm * 32 + mi * 16 + half * 8 + rq;
                    st_s [rowl * 4 + wn] = s;
                    st_ss[rowl * 4 + wn] = ss;
                }
            }
        __syncthreads();
#pragma unroll
        for (int mi = 0; mi < 2; mi++)
#pragma unroll
            for (int half = 0; half < 2; half++) {
                int rowl = wm * 32 + mi * 16 + half * 8 + rq;
                int row  = row0 + rowl;
                float S  = st_s[rowl*4] + st_s[rowl*4+1] + st_s[rowl*4+2] + st_s[rowl*4+3];
                float SS = st_ss[rowl*4] + st_ss[rowl*4+1] + st_ss[rowl*4+2] + st_ss[rowl*4+3];
                float mean = S * (1.0f / 192.0f);
                float var  = SS * (1.0f / 192.0f) - mean * mean;
                float inv  = rsqrtf(var + 1e-5f);
#pragma unroll
                for (int ni = 0; ni < 6; ni++) {
                    int col = ccol + ni * 8;
                    float v0 = acc[mi][ni][half * 2 + 0];
                    float v1 = acc[mi][ni][half * 2 + 1];
                    *(float2*)(Cf + (size_t)row * 192 + col) = make_float2(v0, v1);
                    float n0 = (v0 - mean) * inv * lng[col]     + lnb[col];
                    float n1 = (v1 - mean) * inv * lng[col + 1] + lnb[col + 1];
                    *(unsigned*)(Cb + (size_t)row * 192 + col) = packbf(n0, n1);
                }
            }
        return;
    }

#pragma unroll
    for (int mi = 0; mi < 2; mi++) {
#pragma unroll
        for (int half = 0; half < 2; half++) {
            int row = crow0 + mi * 16 + half * 8;
#pragma unroll
            for (int ni = 0; ni < 6; ni++) {
                int col = ccol + ni * 8;
                float v0 = acc[mi][ni][half * 2 + 0] + bias[col];
                float v1 = acc[mi][ni][half * 2 + 1] + bias[col + 1];
                float2 rv = *(const float2*)(res + (size_t)row * N + col);
                *(float2*)(Cf + (size_t)row * N + col) =
                    make_float2(v0 + rv.x, v1 + rv.y);
            }
        }
    }
}

// -------- fc1 GEMM: A (K=192) persisted in smem, loop 4 n-chunks -----------
// out = gelu(A @ f1wT + f1b) -> bf16. 512 thr, 16 warps (4m x 4n).
#define FC1_SMEM_BYTES ((128 * 100 + 3 * 192 * 20) * 4)
__global__ void __launch_bounds__(512)
gemm_fc1(const __nv_bfloat16* __restrict__ A, const __nv_bfloat16* __restrict__ Wt,
         const float* __restrict__ bias, __nv_bfloat16* __restrict__ Cb)
{
    extern __shared__ unsigned gsm[];
    unsigned* As = gsm;                    // [128][100] full-K A tile
    unsigned* Bs = gsm + 128 * 100;        // [3][192][20]
    const int K = 192;

    const int tid  = threadIdx.x;
    const int lane = tid & 31, warp = tid >> 5;
    const int wm = warp & 3, wn = warp >> 2;
    const int row0 = blockIdx.x * 128;

    const unsigned sA = (unsigned)__cvta_generic_to_shared(As);
    const unsigned sB = (unsigned)__cvta_generic_to_shared(Bs);

    // A: 128 rows x 96 words = 3072 x 16B chunks; 512 thr x 6
#pragma unroll
    for (int i = 0; i < 6; i++) {
        int id = tid + i * 512;
        int r = id / 24, c4 = (id % 24) * 4;
        CP16(sA + (unsigned)(r * 100 + c4) * 4,
             A + (size_t)(row0 + r) * K + c4 * 2);
    }
    CP_COMMIT();

    auto load_B = [&](int col0, int kt, int st) {
        unsigned bOff = sB + (unsigned)(st * 192 * 20) * 4;
        int r = tid >> 2, wc = (tid & 3) * 4;
        CP16(bOff + (unsigned)(r * 20 + wc) * 4,
             Wt + (size_t)(col0 + r) * K + kt + wc * 2);
        if (tid < 256) {
            int id = tid + 512;
            int r2 = id >> 2, wc2 = (id & 3) * 4;
            CP16(bOff + (unsigned)(r2 * 20 + wc2) * 4,
                 Wt + (size_t)(col0 + r2) * K + kt + wc2 * 2);
        }
        CP_COMMIT();
    };

    const int a_row_sel = lane & 15;
    const int a_k_sel   = (lane >> 4) * 4;
    const int b_row_sel = (lane & 7) + (lane >> 4) * 8;
    const int b_k_sel   = ((lane >> 3) & 1) * 4;
    const int rb0 = wm * 32, cb0 = wn * 48;
    const int rq = lane >> 2, tq = lane & 3;

#pragma unroll 1
    for (int nb = 0; nb < 4; nb++) {
        const int col0 = nb * 192;
        load_B(col0, 0, 0);
        load_B(col0, 32, 1);

        float acc[2][6][4];
#pragma unroll
        for (int i = 0; i < 2; i++)
#pragma unroll
            for (int j = 0; j < 6; j++)
#pragma unroll
                for (int t = 0; t < 4; t++) acc[i][j][t] = 0.f;

        int st = 0;
        for (int t = 0; t < 6; t++) {
            if (t + 1 < 6) CP_WAIT1(); else CP_WAIT0();
            __syncthreads();
            if (t + 2 < 6) {
                int st2 = st + 2; if (st2 >= 3) st2 -= 3;
                load_B(col0, (t + 2) << 5, st2);
            }
            const unsigned sBst = sB + (unsigned)(st * 192 * 20) * 4;
            const int kbase = t * 16;   // words
#pragma unroll
            for (int ks = 0; ks < 2; ks++) {
                const int koff = ks * 8;
                unsigned af[2][4], bf[6][2];
#pragma unroll
                for (int mi = 0; mi < 2; mi++) {
                    unsigned addr = sA +
                        (unsigned)(((rb0 + mi * 16 + a_row_sel) * 100 +
                                    kbase + a_k_sel + koff) * 4);
                    LDSM_X4(af[mi][0], af[mi][1], af[mi][2], af[mi][3], addr);
                }
#pragma unroll
                for (int g = 0; g < 3; g++) {
                    unsigned r0, r1, r2, r3;
                    unsigned addr = sBst +
                        (unsigned)(((cb0 + g * 16 + b_row_sel) * 20 + b_k_sel + koff) * 4);
                    LDSM_X4(r0, r1, r2, r3, addr);
                    bf[g * 2 + 0][0] = r0; bf[g * 2 + 0][1] = r1;
                    bf[g * 2 + 1][0] = r2; bf[g * 2 + 1][1] = r3;
                }
#pragma unroll
                for (int mi = 0; mi < 2; mi++)
#pragma unroll
                    for (int ni = 0; ni < 6; ni++)
                        mma_bf16(acc[mi][ni], af[mi], bf[ni]);
            }
            if (++st == 3) st = 0;
        }

        const int crow0 = row0 + wm * 32 + rq;
        const int ccol  = col0 + wn * 48 + tq * 2;
#pragma unroll
        for (int mi = 0; mi < 2; mi++) {
#pragma unroll
            for (int half = 0; half < 2; half++) {
                int row = crow0 + mi * 16 + half * 8;
#pragma unroll
                for (int ni = 0; ni < 6; ni++) {
                    int col = ccol + ni * 8;
                    float v0 = acc[mi][ni][half * 2 + 0] + bias[col];
                    float v1 = acc[mi][ni][half * 2 + 1] + bias[col + 1];
                    *(unsigned*)(Cb + (size_t)row * HID + col) =
                        packbf(gelu_f(v0), gelu_f(v1));
                }
            }
        }
    }
}

// ---------------- attention: full bf16, m16n8k16 + ldmatrix ----------------
#define KS_OFF  0
#define VT_OFF  (64 * 20)
#define QS_OFF  (VT_OFF + 32 * 36)
#define PW_OFF  (QS_OFF + 128 * 20)
#define BT_OFF  (PW_OFF + 8 * 16 * 36)
#define ATTN_SMEM_WORDS (BT_OFF + 343)
__global__ void __launch_bounds__(256)
attn_mma_kernel(const __nv_bfloat16* __restrict__ q, const __nv_bfloat16* __restrict__ kbuf,
                const __nv_bfloat16* __restrict__ vbuf, const float* __restrict__ btab,
                __nv_bfloat16* __restrict__ o)
{
    extern __shared__ unsigned sm[];
    unsigned* Ks = sm + KS_OFF;
    unsigned* Vt = sm + VT_OFF;
    unsigned* Qs = sm + QS_OFF;
    float*    bt = (float*)(sm + BT_OFF);

    const int win  = blockIdx.x / NHD;
    const int head = blockIdx.x % NHD;
    const int tid = threadIdx.x, lane = tid & 31, w = tid >> 5;
    const int rq = lane >> 2, tq = lane & 3;
    const unsigned smem_u = (unsigned)__cvta_generic_to_shared(sm);

    const __nv_bfloat16* kb = kbuf + (size_t)(win * NHD + head) * NP * HD;
    const __nv_bfloat16* vb = vbuf + (size_t)(win * NHD + head) * NP * HD;
    for (int i = tid; i < 64 * 16; i += 256) {
        int m = i >> 4, wp = i & 15;
        Ks[m * 20 + wp] = ((const unsigned*)kb)[i];
    }
    for (int i = tid; i < 32 * 32; i += 256) {
        int c = i >> 5, mp = i & 31;
        Vt[c * 36 + mp] = packbf(__bfloat162float(vb[(2 * mp) * 32 + c]),
                                 __bfloat162float(vb[(2 * mp + 1) * 32 + c]));
    }
    for (int i = tid; i < 343; i += 256) bt[i] = btab[i * NHD + head];

    const int wz = win >> 6, wy = (win >> 3) & 7, wx = win & 7;
    const int wbase = wz * 32768 + wy * 512 + wx * 8;

    const int a_row_sel = lane & 15;
    const int a_k_sel   = (lane >> 4) * 4;
    const int b_row_sel = (lane & 7) + (lane >> 4) * 8;
    const int b_k_sel   = ((lane >> 3) & 1) * 4;
    const unsigned pme_u = smem_u + (unsigned)(PW_OFF + w * 16 * 36) * 4;
    unsigned* Pme = sm + PW_OFF + w * 16 * 36;

#pragma unroll 1
    for (int p = 0; p < 4; p++) {
        __syncthreads();
#pragma unroll
        for (int i = 0; i < 2; i++) {
            int idx = tid + i * 256;
            int r = idx >> 2, wc = (idx & 3) * 4;
            int n = p * 128 + r;
            int l = wbase + (n >> 6) * 4096 + ((n >> 3) & 7) * 64 + (n & 7);
            uint4 v4 = *(const uint4*)(q + (size_t)l * C + head * HD + wc * 2);
            *(uint4*)&Qs[r * 20 + wc] = v4;
        }
        __syncthreads();

        float s[8][4];
#pragma unroll
        for (int j = 0; j < 8; j++)
#pragma unroll
            for (int t = 0; t < 4; t++) s[j][t] = 0.f;

#pragma unroll
        for (int kc = 0; kc < 2; kc++) {
            unsigned a[4];
            LDSM_X4(a[0], a[1], a[2], a[3],
                    smem_u + (unsigned)((QS_OFF + (w * 16 + a_row_sel) * 20 +
                                         a_k_sel + kc * 8) * 4));
            unsigned bf[8][2];
#pragma unroll
            for (int g = 0; g < 4; g++) {
                unsigned r0, r1, r2, r3;
                LDSM_X4(r0, r1, r2, r3,
                        smem_u + (unsigned)((KS_OFF + (g * 16 + b_row_sel) * 20 +
                                             b_k_sel + kc * 8) * 4));
                bf[g * 2 + 0][0] = r0; bf[g * 2 + 0][1] = r1;
                bf[g * 2 + 1][0] = r2; bf[g * 2 + 1][1] = r3;
            }
#pragma unroll
            for (int j = 0; j < 8; j++)
                mma_bf16(s[j], a, bf[j]);
        }

        const int n0 = p * 128 + w * 16 + rq;
        const int n1 = n0 + 8;
        int qb0, qb1;
        {
            int zz = n0 >> 6, yy = (n0 >> 3) & 7, xx = n0 & 7;
            qb0 = ((zz >> 1) + 3) * 49 + ((yy >> 1) + 3) * 7 + (xx >> 1) + 3;
            zz = n1 >> 6; yy = (n1 >> 3) & 7; xx = n1 & 7;
            qb1 = ((zz >> 1) + 3) * 49 + ((yy >> 1) + 3) * 7 + (xx >> 1) + 3;
        }
        float mx0 = -1e30f, mx1 = -1e30f;
#pragma unroll
        for (int j = 0; j < 8; j++) {
#pragma unroll
            for (int s2 = 0; s2 < 2; s2++) {
                int m = j * 8 + tq * 2 + s2;
                int koff = (m >> 4) * 49 + ((m >> 2) & 3) * 7 + (m & 3);
                s[j][s2]     += bt[qb0 - koff];
                s[j][2 + s2] += bt[qb1 - koff];
                mx0 = fmaxf(mx0, s[j][s2]);
                mx1 = fmaxf(mx1, s[j][2 + s2]);
            }
        }
        mx0 = fmaxf(mx0, __shfl_xor_sync(0xffffffffu, mx0, 1));
        mx0 = fmaxf(mx0, __shfl_xor_sync(0xffffffffu, mx0, 2));
        mx1 = fmaxf(mx1, __shfl_xor_sync(0xffffffffu, mx1, 1));
        mx1 = fmaxf(mx1, __shfl_xor_sync(0xffffffffu, mx1, 2));
        float sum0 = 0.f, sum1 = 0.f;
#pragma unroll
        for (int j = 0; j < 8; j++) {
#pragma unroll
            for (int s2 = 0; s2 < 2; s2++) {
                s[j][s2]     = __expf(s[j][s2]     - mx0);
                s[j][2 + s2] = __expf(s[j][2 + s2] - mx1);
                sum0 += s[j][s2];
                sum1 += s[j][2 + s2];
            }
        }
        sum0 += __shfl_xor_sync(0xffffffffu, sum0, 1);
        sum0 += __shfl_xor_sync(0xffffffffu, sum0, 2);
        sum1 += __shfl_xor_sync(0xffffffffu, sum1, 1);
        sum1 += __shfl_xor_sync(0xffffffffu, sum1, 2);
        const float inv0 = 1.0f / sum0, inv1 = 1.0f / sum1;

#pragma unroll
        for (int j = 0; j < 8; j++) {
            Pme[rq * 36 + j * 4 + tq]       = packbf(s[j][0] * inv0, s[j][1] * inv0);
            Pme[(rq + 8) * 36 + j * 4 + tq] = packbf(s[j][2] * inv1, s[j][3] * inv1);
        }
        __syncwarp();

        float oa[4][4];
#pragma unroll
        for (int j = 0; j < 4; j++)
#pragma unroll
            for (int t = 0; t < 4; t++) oa[j][t] = 0.f;

#pragma unroll
        for (int kc = 0; kc < 4; kc++) {
            unsigned a[4];
            LDSM_X4(a[0], a[1], a[2], a[3],
                    pme_u + (unsigned)((a_row_sel * 36 + a_k_sel + kc * 8) * 4));
            unsigned bf[4][2];
#pragma unroll
            for (int g = 0; g < 2; g++) {
                unsigned r0, r1, r2, r3;
                LDSM_X4(r0, r1, r2, r3,
                        smem_u + (unsigned)((VT_OFF + (g * 16 + b_row_sel) * 36 +
                                             b_k_sel + kc * 8) * 4));
                bf[g * 2 + 0][0] = r0; bf[g * 2 + 0][1] = r1;
                bf[g * 2 + 1][0] = r2; bf[g * 2 + 1][1] = r3;
            }
#pragma unroll
            for (int jn = 0; jn < 4; jn++)
                mma_bf16(oa[jn], a, bf[jn]);
        }

        const int l0 = wbase + (n0 >> 6) * 4096 + ((n0 >> 3) & 7) * 64 + (n0 & 7);
        const int l1 = wbase + (n1 >> 6) * 4096 + ((n1 >> 3) & 7) * 64 + (n1 & 7);
        __nv_bfloat16* o0 = o + (size_t)l0 * C + head * HD + tq * 2;
        __nv_bfloat16* o1 = o + (size_t)l1 * C + head * HD + tq * 2;
#pragma unroll
        for (int jn = 0; jn < 4; jn++) {
            *(unsigned*)(o0 + jn * 8) = packbf(oa[jn][0], oa[jn][1]);
            *(unsigned*)(o1 + jn * 8) = packbf(oa[jn][2], oa[jn][3]);
        }
    }
}

// ---------------- depthwise 3x3x3 conv (bf16 io + bf16 weights) ------------
__global__ void dwconv_kernel(const __nv_bfloat16* __restrict__ hid,
                              const float* __restrict__ bias,
                              __nv_bfloat16* __restrict__ hdn)
{
    const int c4  = threadIdx.x;
    const int bid = blockIdx.x;
    const int x0  = (bid & 7) * 8;
    const int y0  = ((bid >> 3) & 31) * 2;
    const int z   = bid >> 8;

    float4 acc[2][8];
#pragma unroll
    for (int yi = 0; yi < 2; yi++)
#pragma unroll
        for (int i = 0; i < 8; i++) acc[yi][i] = make_float4(0.f, 0.f, 0.f, 0.f);

    for (int kd = 0; kd < 3; kd++) {
        int zz = z + kd - 1;
        if (zz < 0 || zz >= DD) continue;
#pragma unroll
        for (int r = 0; r < 4; r++) {
            int yy = y0 - 1 + r;
            if (yy < 0 || yy >= HHH) continue;
            const __nv_bfloat16* base =
                hid + ((size_t)(zz * HHH + yy) * WWW) * HID + c4 * 4;
            float4 hv[10];
#pragma unroll
            for (int i = 0; i < 10; i++) {
                int xx = x0 - 1 + i;
                hv[i] = (xx >= 0 && xx < WWW) ? ldbf4(base + (size_t)xx * HID)
                                              : make_float4(0.f, 0.f, 0.f, 0.f);
            }
#pragma unroll
            for (int yi = 0; yi < 2; yi++) {
                int kh = r - yi;
                if (kh < 0 || kh > 2) continue;
#pragma unroll
                for (int kw = 0; kw < 3; kw++) {
                    float4 wv = ldbf4(g_dwwb + ((kd * 3 + kh) * 3 + kw) * HID + c4 * 4);
#pragma unroll
                    for (int xi = 0; xi < 8; xi++) {
                        acc[yi][xi].x += hv[xi + kw].x * wv.x;
                        acc[yi][xi].y += hv[xi + kw].y * wv.y;
                        acc[yi][xi].z += hv[xi + kw].z * wv.z;
                        acc[yi][xi].w += hv[xi + kw].w * wv.w;
                    }
                }
            }
        }
    }
    float4 bv = *(const float4*)(bias + c4 * 4);
#pragma unroll
    for (int yi = 0; yi < 2; yi++) {
#pragma unroll
        for (int xi = 0; xi < 8; xi++) {
            size_t idx = ((size_t)((z * HHH + y0 + yi) * WWW + x0 + xi)) * HID + c4 * 4;
            float4 h0 = ldbf4(hid + idx);
            float4 o;
            o.x = h0.x + gelu_f(acc[yi][xi].x + bv.x);
            o.y = h0.y + gelu_f(acc[yi][xi].y + bv.y);
            o.z = h0.z + gelu_f(acc[yi][xi].z + bv.z);
            o.w = h0.w + gelu_f(acc[yi][xi].w + bv.w);
            stbf4(hdn + idx, o);
        }
    }
}

// ---------------- launch ----------------------------------------------------
static void* sym_addr(const void* sym) {
    void* p = nullptr;
    cudaGetSymbolAddress(&p, sym);
    return p;
}

extern "C" void kernel_launch(void* const* d_in, const int* in_sizes, int n_in,
                              void* d_out, int out_size)
{
    const float* x    = (const float*)d_in[0];
    const float* n1g  = (const float*)d_in[1];
    const float* n1b  = (const float*)d_in[2];
    const float* q_w  = (const float*)d_in[3];
    const float* q_b  = (const float*)d_in[4];
    const float* kv_w = (const float*)d_in[5];
    const float* kv_b = (const float*)d_in[6];
    const float* btab = (const float*)d_in[7];
    const float* p_w  = (const float*)d_in[8];
    const float* p_b  = (const float*)d_in[9];
    const float* n2g  = (const float*)d_in[10];
    const float* n2b  = (const float*)d_in[11];
    const float* f1w  = (const float*)d_in[12];
    const float* f1b  = (const float*)d_in[13];
    const float* dww  = (const float*)d_in[14];
    const float* dwb  = (const float*)d_in[15];
    const float* f2w  = (const float*)d_in[16];
    const float* f2b  = (const float*)d_in[17];
    float* out = (float*)d_out;

    __nv_bfloat16* xnb  = (__nv_bfloat16*)sym_addr(g_xnb);
    __nv_bfloat16* qb_  = (__nv_bfloat16*)sym_addr(g_qb);
    __nv_bfloat16* kb_  = (__nv_bfloat16*)sym_addr(g_kb);
    __nv_bfloat16* vb_  = (__nv_bfloat16*)sym_addr(g_vb2);
    __nv_bfloat16* ob   = (__nv_bfloat16*)sym_addr(g_ob);
    float*         x1   = (float*)sym_addr(g_x1);
    __nv_bfloat16* hidb = (__nv_bfloat16*)sym_addr(g_hidb);
    __nv_bfloat16* hdnb = (__nv_bfloat16*)sym_addr(g_hdnb);
    __nv_bfloat16* pwT  = (__nv_bfloat16*)sym_addr(g_pwT);
    __nv_bfloat16* f1wT = (__nv_bfloat16*)sym_addr(g_f1wT);
    __nv_bfloat16* f2wT = (__nv_bfloat16*)sym_addr(g_f2wT);

    const int attn_smem = ATTN_SMEM_WORDS * 4;
    cudaFuncSetAttribute(attn_mma_kernel,
                         cudaFuncAttributeMaxDynamicSharedMemorySize, attn_smem);
    cudaFuncSetAttribute(gemm_qkv,
                         cudaFuncAttributeMaxDynamicSharedMemorySize, QKV_SMEM_BYTES);
    cudaFuncSetAttribute(gemm192<1>,
                         cudaFuncAttributeMaxDynamicSharedMemorySize, G192_SMEM_BYTES);
    cudaFuncSetAttribute(gemm192<3>,
                         cudaFuncAttributeMaxDynamicSharedMemorySize, G192_SMEM_BYTES);
    cudaFuncSetAttribute(gemm_fc1,
                         cudaFuncAttributeMaxDynamicSharedMemorySize, FC1_SMEM_BYTES);

    // 0) weight prep
    prep_kernel<<<(PREP_R4 + 255) / 256, 256>>>(q_w, q_b, kv_w, kv_b, p_w, f1w, f2w, dww);
    // 1) LN1 -> bf16
    ln_kernel<<<L / 8, 256>>>(x, n1g, n1b, xnb);
    // 2) fused q + kv projection
    gemm_qkv<<<dim3(4, L / 128), 128, QKV_SMEM_BYTES>>>(xnb, qb_, kb_, vb_);
    // 3) windowed attention (ldmatrix fragment loads)
    attn_mma_kernel<<<NWIN * NHD, 256, attn_smem>>>(qb_, kb_, vb_, btab, ob);
    // 4) proj + residual + fused LN2
    gemm192<3><<<dim3(1, L / 128), 512, G192_SMEM_BYTES>>>(
        ob, pwT, p_b, x, x1, xnb, n2g, n2b, C, C);
    // 5) hid = gelu(xn @ fc1_w + fc1_b)   [A persisted in smem, read once]
    gemm_fc1<<<L / 128, 512, FC1_SMEM_BYTES>>>(xnb, f1wT, f1b, hidb);
    // 6) hdn = hid + gelu(dwconv(hid) + dw_b)
    dwconv_kernel<<<(DD * HHH * WWW) / 16, 192>>>(hidb, dwb, hdnb);
    // 7) out = x1 + hdn @ fc2_w + fc2_b
    gemm192<1><<<dim3(1, L / 128), 512, G192_SMEM_BYTES>>>(
        hdnb, f2wT, f2b, x1, out, nullptr, nullptr, nullptr, C, HID);
}

// round 14
// speedup vs baseline: 1.7056x; 1.0072x over previous
#include <cuda_runtime.h>
#include <cuda_bf16.h>
#include <math.h>

// ---------------- problem constants ----------------
#define L     131072
#define C     192
#define NHD   6
#define HD    32
#define NWIN  256
#define NP    64
#define HID   768
#define DD    32
#define HHH   64
#define WWW   64

// ---------------- scratch ----------------
__device__ __nv_bfloat16 g_xnb [L * C];
__device__ __nv_bfloat16 g_qb  [L * C];
__device__ __nv_bfloat16 g_kb  [NWIN * NHD * NP * HD];
__device__ __nv_bfloat16 g_vb2 [NWIN * NHD * NP * HD];
__device__ __nv_bfloat16 g_ob  [L * C];
__device__ float         g_x1  [L * C];
__device__ __nv_bfloat16 g_hidb[L * HID];
__device__ __nv_bfloat16 g_hdnb[L * HID];
__device__ __nv_bfloat16 g_qkvT[256 * C];
__device__ float         g_qkvb[256];
__device__ __nv_bfloat16 g_pwT [C * C];
__device__ __nv_bfloat16 g_f1wT[HID * C];
__device__ __nv_bfloat16 g_f2wT[C * HID];
__device__ __nv_bfloat16 g_dwwb[27 * HID];

__device__ __forceinline__ float gelu_f(float v) {
    return 0.5f * v * (1.0f + erff(v * 0.70710678118654752f));
}

__device__ __forceinline__ void mma_bf16(float* d, const unsigned* a, const unsigned* b) {
    asm volatile(
        "mma.sync.aligned.m16n8k16.row.col.f32.bf16.bf16.f32 "
        "{%0,%1,%2,%3},{%4,%5,%6,%7},{%8,%9},{%0,%1,%2,%3};"
        : "+f"(d[0]), "+f"(d[1]), "+f"(d[2]), "+f"(d[3])
        : "r"(a[0]), "r"(a[1]), "r"(a[2]), "r"(a[3]), "r"(b[0]), "r"(b[1]));
}

#define LDSM_X4(r0, r1, r2, r3, addr) \
    asm volatile("ldmatrix.sync.aligned.m8n8.x4.shared.b16 {%0,%1,%2,%3}, [%4];" \
                 : "=r"(r0), "=r"(r1), "=r"(r2), "=r"(r3) : "r"(addr))

#define CP16(dst_smem_u32, src_ptr) \
    asm volatile("cp.async.cg.shared.global [%0], [%1], 16;\n" \
                 :: "r"(dst_smem_u32), "l"(src_ptr))
#define CP_COMMIT() asm volatile("cp.async.commit_group;\n" ::: "memory")
#define CP_WAIT1()  asm volatile("cp.async.wait_group 1;\n" ::: "memory")
#define CP_WAIT0()  asm volatile("cp.async.wait_group 0;\n" ::: "memory")

__device__ __forceinline__ float4 ldbf4(const __nv_bfloat16* p) {
    uint2 u = *(const uint2*)p;
    float2 a = __bfloat1622float2(*(__nv_bfloat162*)&u.x);
    float2 b = __bfloat1622float2(*(__nv_bfloat162*)&u.y);
    return make_float4(a.x, a.y, b.x, b.y);
}
__device__ __forceinline__ void stbf4(__nv_bfloat16* p, float4 v) {
    uint2 u;
    *(__nv_bfloat162*)&u.x = __floats2bfloat162_rn(v.x, v.y);
    *(__nv_bfloat162*)&u.y = __floats2bfloat162_rn(v.z, v.w);
    *(uint2*)p = u;
}
__device__ __forceinline__ unsigned packbf(float a, float b) {
    __nv_bfloat162 t = __floats2bfloat162_rn(a, b);
    return *(unsigned*)&t;
}

// ------------- prep ------------
#define PREP_R0 (256 * 192)
#define PREP_R1 (PREP_R0 + 192 * 192)
#define PREP_R2 (PREP_R1 + 768 * 192)
#define PREP_R3 (PREP_R2 + 192 * 768)
#define PREP_R4 (PREP_R3 + 27 * 768)
__global__ void prep_kernel(const float* __restrict__ q_w, const float* __restrict__ q_b,
                            const float* __restrict__ kv_w, const float* __restrict__ kv_b,
                            const float* __restrict__ p_w, const float* __restrict__ f1w,
                            const float* __restrict__ f2w, const float* __restrict__ dww)
{
    const float qscale = 0.17677669529663687f;
    int id = blockIdx.x * 256 + threadIdx.x;
    if (id < 256) {
        float b = 0.f;
        if (id < 192)      b = q_b[id] * qscale;
        else if (id < 240) b = kv_b[id - 192];
        g_qkvb[id] = b;
    }
    if (id < PREP_R0) {
        int n = id / 192, k = id % 192;
        float v = 0.f;
        if (n < 192)      v = q_w[k * 192 + n] * qscale;
        else if (n < 240) v = kv_w[k * 48 + (n - 192)];
        g_qkvT[n * 192 + k] = __float2bfloat16(v);
    } else if (id < PREP_R1) {
        int e = id - PREP_R0, n = e / 192, k = e % 192;
        g_pwT[n * 192 + k] = __float2bfloat16(p_w[k * 192 + n]);
    } else if (id < PREP_R2) {
        int e = id - PREP_R1, n = e / 192, k = e % 192;
        g_f1wT[n * 192 + k] = __float2bfloat16(f1w[k * 768 + n]);
    } else if (id < PREP_R3) {
        int e = id - PREP_R2, n = e / 768, k = e % 768;
        g_f2wT[n * 768 + k] = __float2bfloat16(f2w[k * 192 + n]);
    } else if (id < PREP_R4) {
        int e = id - PREP_R3;
        g_dwwb[e] = __float2bfloat16(dww[e]);
    }
}

// ---------------- LayerNorm (fp32 in, bf16 out) — LN1 only -----------------
__global__ void ln_kernel(const float* __restrict__ x, const float* __restrict__ g,
                          const float* __restrict__ b, __nv_bfloat16* __restrict__ y)
{
    int lane = threadIdx.x & 31;
    int wi   = threadIdx.x >> 5;
    int l    = blockIdx.x * 8 + wi;
    const float* row = x + (size_t)l * C;
    float v[6];
    float s = 0.f, ss = 0.f;
#pragma unroll
    for (int i = 0; i < 6; i++) {
        v[i] = row[lane + 32 * i];
        s  += v[i];
        ss += v[i] * v[i];
    }
#pragma unroll
    for (int off = 16; off > 0; off >>= 1) {
        s  += __shfl_xor_sync(0xffffffffu, s,  off);
        ss += __shfl_xor_sync(0xffffffffu, ss, off);
    }
    float mean = s * (1.0f / C);
    float var  = ss * (1.0f / C) - mean * mean;
    float inv  = rsqrtf(var + 1e-5f);
    __nv_bfloat16* yr = y + (size_t)l * C;
#pragma unroll
    for (int i = 0; i < 6; i++) {
        int c = lane + 32 * i;
        yr[c] = __float2bfloat16((v[i] - mean) * inv * g[c] + b[c]);
    }
}

// -------- fused q+kv GEMM: A persisted (K=192), loop 2 n-chunks of 128 -----
// 512 thr, 16 warps (4m x 4n), warp tile 32x32; scatter epilogue.
#define QKV_SMEM_BYTES ((128 * 100 + 3 * 128 * 20) * 4)
__global__ void __launch_bounds__(512)
gemm_qkv(const __nv_bfloat16* __restrict__ A,
         __nv_bfloat16* __restrict__ qout, __nv_bfloat16* __restrict__ ko,
         __nv_bfloat16* __restrict__ vo)
{
    extern __shared__ unsigned gsm[];
    unsigned* As = gsm;                    // [128][100] full-K A
    unsigned* Bs = gsm + 128 * 100;        // [3][128][20]
    const int K = 192;

    const int tid  = threadIdx.x;
    const int lane = tid & 31, warp = tid >> 5;
    const int wm = warp & 3, wn = warp >> 2;
    const int row0 = blockIdx.x * 128;

    const unsigned sA = (unsigned)__cvta_generic_to_shared(As);
    const unsigned sB = (unsigned)__cvta_generic_to_shared(Bs);
    const __nv_bfloat16* Wt = g_qkvT;

    // A: 128 x 96 words = 3072 x 16B; 512 thr x 6
#pragma unroll
    for (int i = 0; i < 6; i++) {
        int id = tid + i * 512;
        int r = id / 24, c4 = (id % 24) * 4;
        CP16(sA + (unsigned)(r * 100 + c4) * 4,
             A + (size_t)(row0 + r) * K + c4 * 2);
    }
    CP_COMMIT();

    auto load_B = [&](int col0, int kt, int st) {
        unsigned bOff = sB + (unsigned)(st * 128 * 20) * 4;
        int r = tid >> 2, wc = (tid & 3) * 4;
        CP16(bOff + (unsigned)(r * 20 + wc) * 4,
             Wt + (size_t)(col0 + r) * K + kt + wc * 2);
        CP_COMMIT();
    };

    const int a_row_sel = lane & 15;
    const int a_k_sel   = (lane >> 4) * 4;
    const int b_row_sel = (lane & 7) + (lane >> 4) * 8;
    const int b_k_sel   = ((lane >> 3) & 1) * 4;
    const int rb0 = wm * 32, cb0 = wn * 32;
    const int rq = lane >> 2, tq = lane & 3;

#pragma unroll 1
    for (int nb = 0; nb < 2; nb++) {
        const int col0 = nb * 128;
        load_B(col0, 0, 0);
        load_B(col0, 32, 1);

        float acc[2][4][4];
#pragma unroll
        for (int i = 0; i < 2; i++)
#pragma unroll
            for (int j = 0; j < 4; j++)
#pragma unroll
                for (int t = 0; t < 4; t++) acc[i][j][t] = 0.f;

        int st = 0;
        for (int t = 0; t < 6; t++) {
            if (t + 1 < 6) CP_WAIT1(); else CP_WAIT0();
            __syncthreads();
            if (t + 2 < 6) {
                int st2 = st + 2; if (st2 >= 3) st2 -= 3;
                load_B(col0, (t + 2) << 5, st2);
            }
            const unsigned sBst = sB + (unsigned)(st * 128 * 20) * 4;
            const int kbase = t * 16;
#pragma unroll
            for (int ks = 0; ks < 2; ks++) {
                const int koff = ks * 8;
                unsigned af[2][4], bf[4][2];
#pragma unroll
                for (int mi = 0; mi < 2; mi++) {
                    unsigned addr = sA +
                        (unsigned)(((rb0 + mi * 16 + a_row_sel) * 100 +
                                    kbase + a_k_sel + koff) * 4);
                    LDSM_X4(af[mi][0], af[mi][1], af[mi][2], af[mi][3], addr);
                }
#pragma unroll
                for (int g = 0; g < 2; g++) {
                    unsigned r0, r1, r2, r3;
                    unsigned addr = sBst +
                        (unsigned)(((cb0 + g * 16 + b_row_sel) * 20 + b_k_sel + koff) * 4);
                    LDSM_X4(r0, r1, r2, r3, addr);
                    bf[g * 2 + 0][0] = r0; bf[g * 2 + 0][1] = r1;
                    bf[g * 2 + 1][0] = r2; bf[g * 2 + 1][1] = r3;
                }
#pragma unroll
                for (int mi = 0; mi < 2; mi++)
#pragma unroll
                    for (int ni = 0; ni < 4; ni++)
                        mma_bf16(acc[mi][ni], af[mi], bf[ni]);
            }
            if (++st == 3) st = 0;
        }

        const int crow0 = row0 + wm * 32 + rq;
        const int ccol  = col0 + wn * 32 + tq * 2;
#pragma unroll
        for (int mi = 0; mi < 2; mi++) {
#pragma unroll
            for (int half = 0; half < 2; half++) {
                int row = crow0 + mi * 16 + half * 8;
#pragma unroll
                for (int ni = 0; ni < 4; ni++) {
                    int col = ccol + ni * 8;
                    float v0 = acc[mi][ni][half * 2 + 0] + g_qkvb[col];
                    float v1 = acc[mi][ni][half * 2 + 1] + g_qkvb[col + 1];
                    if (col < 192) {
                        *(unsigned*)(qout + (size_t)row * 192 + col) = packbf(v0, v1);
                    } else if (col < 240) {
                        int j = col - 192, jg = j >> 2, tt = j & 3;
                        __nv_bfloat16* dst = (jg < 6) ? ko : vo;
                        int head = (jg < 6) ? jg : jg - 6;
                        int z = row >> 12, y = (row >> 6) & 63, xq = row & 63;
                        int win = ((z >> 3) << 6) | ((y >> 3) << 3) | (xq >> 3);
                        int m = (((z & 7) >> 1) << 4) | (((y & 7) >> 1) << 2) | ((xq & 7) >> 1);
                        int sub = ((z & 1) << 2) | ((y & 1) << 1) | (xq & 1);
                        *(unsigned*)&dst[(((size_t)(win * 6 + head)) * 64 + m) * 32 + sub * 4 + tt] =
                            packbf(v0, v1);
                    }
                }
            }
        }
    }
}

// -------- wide GEMM 128x192, 512 thr; EPI: 1=+res fp32, 3=+res+LN fused ----
#define G192_SMEM_BYTES ((3 * (128 * 20 + 192 * 20)) * 4)
template <int EPI>
__global__ void __launch_bounds__(512)
gemm192(const __nv_bfloat16* __restrict__ A, const __nv_bfloat16* __restrict__ Wt,
        const float* __restrict__ bias, const float* __restrict__ res,
        float* __restrict__ Cf, __nv_bfloat16* __restrict__ Cb,
        const float* __restrict__ lng, const float* __restrict__ lnb,
        int N, int K)
{
    extern __shared__ unsigned gsm[];
    unsigned* As = gsm;
    unsigned* Bs = gsm + 3 * 128 * 20;

    const int tid  = threadIdx.x;
    const int lane = tid & 31, warp = tid >> 5;
    const int wm = warp & 3, wn = warp >> 2;
    const int row0 = blockIdx.y * 128, col0 = blockIdx.x * 192;

    float acc[2][6][4];
#pragma unroll
    for (int i = 0; i < 2; i++)
#pragma unroll
        for (int j = 0; j < 6; j++)
#pragma unroll
            for (int t = 0; t < 4; t++) acc[i][j][t] = 0.f;

    const unsigned sA = (unsigned)__cvta_generic_to_shared(As);
    const unsigned sB = (unsigned)__cvta_generic_to_shared(Bs);
    const int ntiles = K >> 5;

    auto load_tile = [&](int kt, int st) {
        unsigned aOff = sA + (unsigned)(st * 128 * 20) * 4;
        {
            int r = tid >> 2, wc = (tid & 3) * 4;
            CP16(aOff + (unsigned)(r * 20 + wc) * 4,
                 A + (size_t)(row0 + r) * K + kt + wc * 2);
        }
        unsigned bOff = sB + (unsigned)(st * 192 * 20) * 4;
        {
            int r = tid >> 2, wc = (tid & 3) * 4;
            CP16(bOff + (unsigned)(r * 20 + wc) * 4,
                 Wt + (size_t)(col0 + r) * K + kt + wc * 2);
            if (tid < 256) {
                int id = tid + 512;
                int r2 = id >> 2, wc2 = (id & 3) * 4;
                CP16(bOff + (unsigned)(r2 * 20 + wc2) * 4,
                     Wt + (size_t)(col0 + r2) * K + kt + wc2 * 2);
            }
        }
        CP_COMMIT();
    };

    load_tile(0, 0);
    load_tile(32, 1);

    const int a_row_sel = lane & 15;
    const int a_k_sel   = (lane >> 4) * 4;
    const int b_row_sel = (lane & 7) + (lane >> 4) * 8;
    const int b_k_sel   = ((lane >> 3) & 1) * 4;
    const int rb0 = wm * 32, cb0 = wn * 48;

    int st = 0;
    for (int t = 0; t < ntiles; t++) {
        if (t + 1 < ntiles) CP_WAIT1(); else CP_WAIT0();
        __syncthreads();
        if (t + 2 < ntiles) {
            int st2 = st + 2; if (st2 >= 3) st2 -= 3;
            load_tile((t + 2) << 5, st2);
        }
        const unsigned sAst = sA + (unsigned)(st * 128 * 20) * 4;
        const unsigned sBst = sB + (unsigned)(st * 192 * 20) * 4;
#pragma unroll
        for (int ks = 0; ks < 2; ks++) {
            const int koff = ks * 8;
            unsigned af[2][4], bf[6][2];
#pragma unroll
            for (int mi = 0; mi < 2; mi++) {
                unsigned addr = sAst +
                    (unsigned)(((rb0 + mi * 16 + a_row_sel) * 20 + a_k_sel + koff) * 4);
                LDSM_X4(af[mi][0], af[mi][1], af[mi][2], af[mi][3], addr);
            }
#pragma unroll
            for (int g = 0; g < 3; g++) {
                unsigned r0, r1, r2, r3;
                unsigned addr = sBst +
                    (unsigned)(((cb0 + g * 16 + b_row_sel) * 20 + b_k_sel + koff) * 4);
                LDSM_X4(r0, r1, r2, r3, addr);
                bf[g * 2 + 0][0] = r0; bf[g * 2 + 0][1] = r1;
                bf[g * 2 + 1][0] = r2; bf[g * 2 + 1][1] = r3;
            }
#pragma unroll
            for (int mi = 0; mi < 2; mi++)
#pragma unroll
                for (int ni = 0; ni < 6; ni++)
                    mma_bf16(acc[mi][ni], af[mi], bf[ni]);
        }
        if (++st == 3) st = 0;
    }

    const int rq = lane >> 2, tq = lane & 3;
    const int crow0 = row0 + wm * 32 + rq;
    const int ccol  = col0 + wn * 48 + tq * 2;

    if (EPI == 3) {
        __syncthreads();
        float* st_s  = (float*)gsm;
        float* st_ss = (float*)gsm + 512;
#pragma unroll
        for (int mi = 0; mi < 2; mi++)
#pragma unroll
            for (int half = 0; half < 2; half++) {
                int row = crow0 + mi * 16 + half * 8;
                float s = 0.f, ss = 0.f;
#pragma unroll
                for (int ni = 0; ni < 6; ni++) {
                    int col = ccol + ni * 8;
                    float2 rv = *(const float2*)(res + (size_t)row * 192 + col);
                    float v0 = acc[mi][ni][half * 2 + 0] + bias[col]     + rv.x;
                    float v1 = acc[mi][ni][half * 2 + 1] + bias[col + 1] + rv.y;
                    acc[mi][ni][half * 2 + 0] = v0;
                    acc[mi][ni][half * 2 + 1] = v1;
                    s += v0 + v1; ss += v0 * v0 + v1 * v1;
                }
                s  += __shfl_xor_sync(0xffffffffu, s, 1);
                s  += __shfl_xor_sync(0xffffffffu, s, 2);
                ss += __shfl_xor_sync(0xffffffffu, ss, 1);
                ss += __shfl_xor_sync(0xffffffffu, ss, 2);
                if (tq == 0) {
                    int rowl = wm * 32 + mi * 16 + half * 8 + rq;
                    st_s [rowl * 4 + wn] = s;
                    st_ss[rowl * 4 + wn] = ss;
                }
            }
        __syncthreads();
#pragma unroll
        for (int mi = 0; mi < 2; mi++)
#pragma unroll
            for (int half = 0; half < 2; half++) {
                int rowl = wm * 32 + mi * 16 + half * 8 + rq;
                int row  = row0 + rowl;
                float S  = st_s[rowl*4] + st_s[rowl*4+1] + st_s[rowl*4+2] + st_s[rowl*4+3];
                float SS = st_ss[rowl*4] + st_ss[rowl*4+1] + st_ss[rowl*4+2] + st_ss[rowl*4+3];
                float mean = S * (1.0f / 192.0f);
                float var  = SS * (1.0f / 192.0f) - mean * mean;
                float inv  = rsqrtf(var + 1e-5f);
#pragma unroll
                for (int ni = 0; ni < 6; ni++) {
                    int col = ccol + ni * 8;
                    float v0 = acc[mi][ni][half * 2 + 0];
                    float v1 = acc[mi][ni][half * 2 + 1];
                    *(float2*)(Cf + (size_t)row * 192 + col) = make_float2(v0, v1);
                    float n0 = (v0 - mean) * inv * lng[col]     + lnb[col];
                    float n1 = (v1 - mean) * inv * lng[col + 1] + lnb[col + 1];
                    *(unsigned*)(Cb + (size_t)row * 192 + col) = packbf(n0, n1);
                }
            }
        return;
    }

#pragma unroll
    for (int mi = 0; mi < 2; mi++) {
#pragma unroll
        for (int half = 0; half < 2; half++) {
            int row = crow0 + mi * 16 + half * 8;
#pragma unroll
            for (int ni = 0; ni < 6; ni++) {
                int col = ccol + ni * 8;
                float v0 = acc[mi][ni][half * 2 + 0] + bias[col];
                float v1 = acc[mi][ni][half * 2 + 1] + bias[col + 1];
                float2 rv = *(const float2*)(res + (size_t)row * N + col);
                *(float2*)(Cf + (size_t)row * N + col) =
                    make_float2(v0 + rv.x, v1 + rv.y);
            }
        }
    }
}

// -------- fc1 GEMM: A (K=192) persisted in smem, loop 4 n-chunks -----------
#define FC1_SMEM_BYTES ((128 * 100 + 3 * 192 * 20) * 4)
__global__ void __launch_bounds__(512)
gemm_fc1(const __nv_bfloat16* __restrict__ A, const __nv_bfloat16* __restrict__ Wt,
         const float* __restrict__ bias, __nv_bfloat16* __restrict__ Cb)
{
    extern __shared__ unsigned gsm[];
    unsigned* As = gsm;
    unsigned* Bs = gsm + 128 * 100;
    const int K = 192;

    const int tid  = threadIdx.x;
    const int lane = tid & 31, warp = tid >> 5;
    const int wm = warp & 3, wn = warp >> 2;
    const int row0 = blockIdx.x * 128;

    const unsigned sA = (unsigned)__cvta_generic_to_shared(As);
    const unsigned sB = (unsigned)__cvta_generic_to_shared(Bs);

#pragma unroll
    for (int i = 0; i < 6; i++) {
        int id = tid + i * 512;
        int r = id / 24, c4 = (id % 24) * 4;
        CP16(sA + (unsigned)(r * 100 + c4) * 4,
             A + (size_t)(row0 + r) * K + c4 * 2);
    }
    CP_COMMIT();

    auto load_B = [&](int col0, int kt, int st) {
        unsigned bOff = sB + (unsigned)(st * 192 * 20) * 4;
        int r = tid >> 2, wc = (tid & 3) * 4;
        CP16(bOff + (unsigned)(r * 20 + wc) * 4,
             Wt + (size_t)(col0 + r) * K + kt + wc * 2);
        if (tid < 256) {
            int id = tid + 512;
            int r2 = id >> 2, wc2 = (id & 3) * 4;
            CP16(bOff + (unsigned)(r2 * 20 + wc2) * 4,
                 Wt + (size_t)(col0 + r2) * K + kt + wc2 * 2);
        }
        CP_COMMIT();
    };

    const int a_row_sel = lane & 15;
    const int a_k_sel   = (lane >> 4) * 4;
    const int b_row_sel = (lane & 7) + (lane >> 4) * 8;
    const int b_k_sel   = ((lane >> 3) & 1) * 4;
    const int rb0 = wm * 32, cb0 = wn * 48;
    const int rq = lane >> 2, tq = lane & 3;

#pragma unroll 1
    for (int nb = 0; nb < 4; nb++) {
        const int col0 = nb * 192;
        load_B(col0, 0, 0);
        load_B(col0, 32, 1);

        float acc[2][6][4];
#pragma unroll
        for (int i = 0; i < 2; i++)
#pragma unroll
            for (int j = 0; j < 6; j++)
#pragma unroll
                for (int t = 0; t < 4; t++) acc[i][j][t] = 0.f;

        int st = 0;
        for (int t = 0; t < 6; t++) {
            if (t + 1 < 6) CP_WAIT1(); else CP_WAIT0();
            __syncthreads();
            if (t + 2 < 6) {
                int st2 = st + 2; if (st2 >= 3) st2 -= 3;
                load_B(col0, (t + 2) << 5, st2);
            }
            const unsigned sBst = sB + (unsigned)(st * 192 * 20) * 4;
            const int kbase = t * 16;
#pragma unroll
            for (int ks = 0; ks < 2; ks++) {
                const int koff = ks * 8;
                unsigned af[2][4], bf[6][2];
#pragma unroll
                for (int mi = 0; mi < 2; mi++) {
                    unsigned addr = sA +
                        (unsigned)(((rb0 + mi * 16 + a_row_sel) * 100 +
                                    kbase + a_k_sel + koff) * 4);
                    LDSM_X4(af[mi][0], af[mi][1], af[mi][2], af[mi][3], addr);
                }
#pragma unroll
                for (int g = 0; g < 3; g++) {
                    unsigned r0, r1, r2, r3;
                    unsigned addr = sBst +
                        (unsigned)(((cb0 + g * 16 + b_row_sel) * 20 + b_k_sel + koff) * 4);
                    LDSM_X4(r0, r1, r2, r3, addr);
                    bf[g * 2 + 0][0] = r0; bf[g * 2 + 0][1] = r1;
                    bf[g * 2 + 1][0] = r2; bf[g * 2 + 1][1] = r3;
                }
#pragma unroll
                for (int mi = 0; mi < 2; mi++)
#pragma unroll
                    for (int ni = 0; ni < 6; ni++)
                        mma_bf16(acc[mi][ni], af[mi], bf[ni]);
            }
            if (++st == 3) st = 0;
        }

        const int crow0 = row0 + wm * 32 + rq;
        const int ccol  = col0 + wn * 48 + tq * 2;
#pragma unroll
        for (int mi = 0; mi < 2; mi++) {
#pragma unroll
            for (int half = 0; half < 2; half++) {
                int row = crow0 + mi * 16 + half * 8;
#pragma unroll
                for (int ni = 0; ni < 6; ni++) {
                    int col = ccol + ni * 8;
                    float v0 = acc[mi][ni][half * 2 + 0] + bias[col];
                    float v1 = acc[mi][ni][half * 2 + 1] + bias[col + 1];
                    *(unsigned*)(Cb + (size_t)row * HID + col) =
                        packbf(gelu_f(v0), gelu_f(v1));
                }
            }
        }
    }
}

// ---------------- attention: full bf16, m16n8k16 + ldmatrix ----------------
#define KS_OFF  0
#define VT_OFF  (64 * 20)
#define QS_OFF  (VT_OFF + 32 * 36)
#define PW_OFF  (QS_OFF + 128 * 20)
#define BT_OFF  (PW_OFF + 8 * 16 * 36)
#define ATTN_SMEM_WORDS (BT_OFF + 343)
__global__ void __launch_bounds__(256, 4)
attn_mma_kernel(const __nv_bfloat16* __restrict__ q, const __nv_bfloat16* __restrict__ kbuf,
                const __nv_bfloat16* __restrict__ vbuf, const float* __restrict__ btab,
                __nv_bfloat16* __restrict__ o)
{
    extern __shared__ unsigned sm[];
    unsigned* Ks = sm + KS_OFF;
    unsigned* Vt = sm + VT_OFF;
    unsigned* Qs = sm + QS_OFF;
    float*    bt = (float*)(sm + BT_OFF);

    const int win  = blockIdx.x / NHD;
    const int head = blockIdx.x % NHD;
    const int tid = threadIdx.x, lane = tid & 31, w = tid >> 5;
    const int rq = lane >> 2, tq = lane & 3;
    const unsigned smem_u = (unsigned)__cvta_generic_to_shared(sm);

    const __nv_bfloat16* kb = kbuf + (size_t)(win * NHD + head) * NP * HD;
    const __nv_bfloat16* vb = vbuf + (size_t)(win * NHD + head) * NP * HD;
    for (int i = tid; i < 64 * 16; i += 256) {
        int m = i >> 4, wp = i & 15;
        Ks[m * 20 + wp] = ((const unsigned*)kb)[i];
    }
    for (int i = tid; i < 32 * 32; i += 256) {
        int c = i >> 5, mp = i & 31;
        Vt[c * 36 + mp] = packbf(__bfloat162float(vb[(2 * mp) * 32 + c]),
                                 __bfloat162float(vb[(2 * mp + 1) * 32 + c]));
    }
    for (int i = tid; i < 343; i += 256) bt[i] = btab[i * NHD + head];

    const int wz = win >> 6, wy = (win >> 3) & 7, wx = win & 7;
    const int wbase = wz * 32768 + wy * 512 + wx * 8;

    const int a_row_sel = lane & 15;
    const int a_k_sel   = (lane >> 4) * 4;
    const int b_row_sel = (lane & 7) + (lane >> 4) * 8;
    const int b_k_sel   = ((lane >> 3) & 1) * 4;
    const unsigned pme_u = smem_u + (unsigned)(PW_OFF + w * 16 * 36) * 4;
    unsigned* Pme = sm + PW_OFF + w * 16 * 36;

#pragma unroll 1
    for (int p = 0; p < 4; p++) {
        __syncthreads();
#pragma unroll
        for (int i = 0; i < 2; i++) {
            int idx = tid + i * 256;
            int r = idx >> 2, wc = (idx & 3) * 4;
            int n = p * 128 + r;
            int l = wbase + (n >> 6) * 4096 + ((n >> 3) & 7) * 64 + (n & 7);
            uint4 v4 = *(const uint4*)(q + (size_t)l * C + head * HD + wc * 2);
            *(uint4*)&Qs[r * 20 + wc] = v4;
        }
        __syncthreads();

        float s[8][4];
#pragma unroll
        for (int j = 0; j < 8; j++)
#pragma unroll
            for (int t = 0; t < 4; t++) s[j][t] = 0.f;

#pragma unroll
        for (int kc = 0; kc < 2; kc++) {
            unsigned a[4];
            LDSM_X4(a[0], a[1], a[2], a[3],
                    smem_u + (unsigned)((QS_OFF + (w * 16 + a_row_sel) * 20 +
                                         a_k_sel + kc * 8) * 4));
            unsigned bf[8][2];
#pragma unroll
            for (int g = 0; g < 4; g++) {
                unsigned r0, r1, r2, r3;
                LDSM_X4(r0, r1, r2, r3,
                        smem_u + (unsigned)((KS_OFF + (g * 16 + b_row_sel) * 20 +
                                             b_k_sel + kc * 8) * 4));
                bf[g * 2 + 0][0] = r0; bf[g * 2 + 0][1] = r1;
                bf[g * 2 + 1][0] = r2; bf[g * 2 + 1][1] = r3;
            }
#pragma unroll
            for (int j = 0; j < 8; j++)
                mma_bf16(s[j], a, bf[j]);
        }

        const int n0 = p * 128 + w * 16 + rq;
        const int n1 = n0 + 8;
        int qb0, qb1;
        {
            int zz = n0 >> 6, yy = (n0 >> 3) & 7, xx = n0 & 7;
            qb0 = ((zz >> 1) + 3) * 49 + ((yy >> 1) + 3) * 7 + (xx >> 1) + 3;
            zz = n1 >> 6; yy = (n1 >> 3) & 7; xx = n1 & 7;
            qb1 = ((zz >> 1) + 3) * 49 + ((yy >> 1) + 3) * 7 + (xx >> 1) + 3;
        }
        float mx0 = -1e30f, mx1 = -1e30f;
#pragma unroll
        for (int j = 0; j < 8; j++) {
#pragma unroll
            for (int s2 = 0; s2 < 2; s2++) {
                int m = j * 8 + tq * 2 + s2;
                int koff = (m >> 4) * 49 + ((m >> 2) & 3) * 7 + (m & 3);
                s[j][s2]     += bt[qb0 - koff];
                s[j][2 + s2] += bt[qb1 - koff];
                mx0 = fmaxf(mx0, s[j][s2]);
                mx1 = fmaxf(mx1, s[j][2 + s2]);
            }
        }
        mx0 = fmaxf(mx0, __shfl_xor_sync(0xffffffffu, mx0, 1));
        mx0 = fmaxf(mx0, __shfl_xor_sync(0xffffffffu, mx0, 2));
        mx1 = fmaxf(mx1, __shfl_xor_sync(0xffffffffu, mx1, 1));
        mx1 = fmaxf(mx1, __shfl_xor_sync(0xffffffffu, mx1, 2));
        float sum0 = 0.f, sum1 = 0.f;
#pragma unroll
        for (int j = 0; j < 8; j++) {
#pragma unroll
            for (int s2 = 0; s2 < 2; s2++) {
                s[j][s2]     = __expf(s[j][s2]     - mx0);
                s[j][2 + s2] = __expf(s[j][2 + s2] - mx1);
                sum0 += s[j][s2];
                sum1 += s[j][2 + s2];
            }
        }
        sum0 += __shfl_xor_sync(0xffffffffu, sum0, 1);
        sum0 += __shfl_xor_sync(0xffffffffu, sum0, 2);
        sum1 += __shfl_xor_sync(0xffffffffu, sum1, 1);
        sum1 += __shfl_xor_sync(0xffffffffu, sum1, 2);
        const float inv0 = 1.0f / sum0, inv1 = 1.0f / sum1;

#pragma unroll
        for (int j = 0; j < 8; j++) {
            Pme[rq * 36 + j * 4 + tq]       = packbf(s[j][0] * inv0, s[j][1] * inv0);
            Pme[(rq + 8) * 36 + j * 4 + tq] = packbf(s[j][2] * inv1, s[j][3] * inv1);
        }
        __syncwarp();

        float oa[4][4];
#pragma unroll
        for (int j = 0; j < 4; j++)
#pragma unroll
            for (int t = 0; t < 4; t++) oa[j][t] = 0.f;

#pragma unroll
        for (int kc = 0; kc < 4; kc++) {
            unsigned a[4];
            LDSM_X4(a[0], a[1], a[2], a[3],
                    pme_u + (unsigned)((a_row_sel * 36 + a_k_sel + kc * 8) * 4));
            unsigned bf[4][2];
#pragma unroll
            for (int g = 0; g < 2; g++) {
                unsigned r0, r1, r2, r3;
                LDSM_X4(r0, r1, r2, r3,
                        smem_u + (unsigned)((VT_OFF + (g * 16 + b_row_sel) * 36 +
                                             b_k_sel + kc * 8) * 4));
                bf[g * 2 + 0][0] = r0; bf[g * 2 + 0][1] = r1;
                bf[g * 2 + 1][0] = r2; bf[g * 2 + 1][1] = r3;
            }
#pragma unroll
            for (int jn = 0; jn < 4; jn++)
                mma_bf16(oa[jn], a, bf[jn]);
        }

        const int l0 = wbase + (n0 >> 6) * 4096 + ((n0 >> 3) & 7) * 64 + (n0 & 7);
        const int l1 = wbase + (n1 >> 6) * 4096 + ((n1 >> 3) & 7) * 64 + (n1 & 7);
        __nv_bfloat16* o0 = o + (size_t)l0 * C + head * HD + tq * 2;
        __nv_bfloat16* o1 = o + (size_t)l1 * C + head * HD + tq * 2;
#pragma unroll
        for (int jn = 0; jn < 4; jn++) {
            *(unsigned*)(o0 + jn * 8) = packbf(oa[jn][0], oa[jn][1]);
            *(unsigned*)(o1 + jn * 8) = packbf(oa[jn][2], oa[jn][3]);
        }
    }
}

// ---------------- depthwise 3x3x3 conv (bf16 io + bf16 weights) ------------
__global__ void dwconv_kernel(const __nv_bfloat16* __restrict__ hid,
                              const float* __restrict__ bias,
                              __nv_bfloat16* __restrict__ hdn)
{
    const int c4  = threadIdx.x;
    const int bid = blockIdx.x;
    const int x0  = (bid & 7) * 8;
    const int y0  = ((bid >> 3) & 31) * 2;
    const int z   = bid >> 8;

    float4 acc[2][8];
#pragma unroll
    for (int yi = 0; yi < 2; yi++)
#pragma unroll
        for (int i = 0; i < 8; i++) acc[yi][i] = make_float4(0.f, 0.f, 0.f, 0.f);

    for (int kd = 0; kd < 3; kd++) {
        int zz = z + kd - 1;
        if (zz < 0 || zz >= DD) continue;
#pragma unroll
        for (int r = 0; r < 4; r++) {
            int yy = y0 - 1 + r;
            if (yy < 0 || yy >= HHH) continue;
            const __nv_bfloat16* base =
                hid + ((size_t)(zz * HHH + yy) * WWW) * HID + c4 * 4;
            float4 hv[10];
#pragma unroll
            for (int i = 0; i < 10; i++) {
                int xx = x0 - 1 + i;
                hv[i] = (xx >= 0 && xx < WWW) ? ldbf4(base + (size_t)xx * HID)
                                              : make_float4(0.f, 0.f, 0.f, 0.f);
            }
#pragma unroll
            for (int yi = 0; yi < 2; yi++) {
                int kh = r - yi;
                if (kh < 0 || kh > 2) continue;
#pragma unroll
                for (int kw = 0; kw < 3; kw++) {
                    float4 wv = ldbf4(g_dwwb + ((kd * 3 + kh) * 3 + kw) * HID + c4 * 4);
#pragma unroll
                    for (int xi = 0; xi < 8; xi++) {
                        acc[yi][xi].x += hv[xi + kw].x * wv.x;
                        acc[yi][xi].y += hv[xi + kw].y * wv.y;
                        acc[yi][xi].z += hv[xi + kw].z * wv.z;
                        acc[yi][xi].w += hv[xi + kw].w * wv.w;
                    }
                }
            }
        }
    }
    float4 bv = *(const float4*)(bias + c4 * 4);
#pragma unroll
    for (int yi = 0; yi < 2; yi++) {
#pragma unroll
        for (int xi = 0; xi < 8; xi++) {
            size_t idx = ((size_t)((z * HHH + y0 + yi) * WWW + x0 + xi)) * HID + c4 * 4;
            float4 h0 = ldbf4(hid + idx);
            float4 o;
            o.x = h0.x + gelu_f(acc[yi][xi].x + bv.x);
            o.y = h0.y + gelu_f(acc[yi][xi].y + bv.y);
            o.z = h0.z + gelu_f(acc[yi][xi].z + bv.z);
            o.w = h0.w + gelu_f(acc[yi][xi].w + bv.w);
            stbf4(hdn + idx, o);
        }
    }
}

// ---------------- launch ----------------------------------------------------
static void* sym_addr(const void* sym) {
    void* p = nullptr;
    cudaGetSymbolAddress(&p, sym);
    return p;
}

extern "C" void kernel_launch(void* const* d_in, const int* in_sizes, int n_in,
                              void* d_out, int out_size)
{
    const float* x    = (const float*)d_in[0];
    const float* n1g  = (const float*)d_in[1];
    const float* n1b  = (const float*)d_in[2];
    const float* q_w  = (const float*)d_in[3];
    const float* q_b  = (const float*)d_in[4];
    const float* kv_w = (const float*)d_in[5];
    const float* kv_b = (const float*)d_in[6];
    const float* btab = (const float*)d_in[7];
    const float* p_w  = (const float*)d_in[8];
    const float* p_b  = (const float*)d_in[9];
    const float* n2g  = (const float*)d_in[10];
    const float* n2b  = (const float*)d_in[11];
    const float* f1w  = (const float*)d_in[12];
    const float* f1b  = (const float*)d_in[13];
    const float* dww  = (const float*)d_in[14];
    const float* dwb  = (const float*)d_in[15];
    const float* f2w  = (const float*)d_in[16];
    const float* f2b  = (const float*)d_in[17];
    float* out = (float*)d_out;

    __nv_bfloat16* xnb  = (__nv_bfloat16*)sym_addr(g_xnb);
    __nv_bfloat16* qb_  = (__nv_bfloat16*)sym_addr(g_qb);
    __nv_bfloat16* kb_  = (__nv_bfloat16*)sym_addr(g_kb);
    __nv_bfloat16* vb_  = (__nv_bfloat16*)sym_addr(g_vb2);
    __nv_bfloat16* ob   = (__nv_bfloat16*)sym_addr(g_ob);
    float*         x1   = (float*)sym_addr(g_x1);
    __nv_bfloat16* hidb = (__nv_bfloat16*)sym_addr(g_hidb);
    __nv_bfloat16* hdnb = (__nv_bfloat16*)sym_addr(g_hdnb);
    __nv_bfloat16* pwT  = (__nv_bfloat16*)sym_addr(g_pwT);
    __nv_bfloat16* f1wT = (__nv_bfloat16*)sym_addr(g_f1wT);
    __nv_bfloat16* f2wT = (__nv_bfloat16*)sym_addr(g_f2wT);

    const int attn_smem = ATTN_SMEM_WORDS * 4;
    cudaFuncSetAttribute(attn_mma_kernel,
                         cudaFuncAttributeMaxDynamicSharedMemorySize, attn_smem);
    cudaFuncSetAttribute(gemm_qkv,
                         cudaFuncAttributeMaxDynamicSharedMemorySize, QKV_SMEM_BYTES);
    cudaFuncSetAttribute(gemm192<1>,
                         cudaFuncAttributeMaxDynamicSharedMemorySize, G192_SMEM_BYTES);
    cudaFuncSetAttribute(gemm192<3>,
                         cudaFuncAttributeMaxDynamicSharedMemorySize, G192_SMEM_BYTES);
    cudaFuncSetAttribute(gemm_fc1,
                         cudaFuncAttributeMaxDynamicSharedMemorySize, FC1_SMEM_BYTES);

    // 0) weight prep
    prep_kernel<<<(PREP_R4 + 255) / 256, 256>>>(q_w, q_b, kv_w, kv_b, p_w, f1w, f2w, dww);
    // 1) LN1 -> bf16
    ln_kernel<<<L / 8, 256>>>(x, n1g, n1b, xnb);
    // 2) fused q + kv projection (A persisted, read once)
    gemm_qkv<<<L / 128, 512, QKV_SMEM_BYTES>>>(xnb, qb_, kb_, vb_);
    // 3) windowed attention (ldmatrix + reg cap)
    attn_mma_kernel<<<NWIN * NHD, 256, attn_smem>>>(qb_, kb_, vb_, btab, ob);
    // 4) proj + residual + fused LN2
    gemm192<3><<<dim3(1, L / 128), 512, G192_SMEM_BYTES>>>(
        ob, pwT, p_b, x, x1, xnb, n2g, n2b, C, C);
    // 5) hid = gelu(xn @ fc1_w + fc1_b)   [A persisted]
    gemm_fc1<<<L / 128, 512, FC1_SMEM_BYTES>>>(xnb, f1wT, f1b, hidb);
    // 6) hdn = hid + gelu(dwconv(hid) + dw_b)
    dwconv_kernel<<<(DD * HHH * WWW) / 16, 192>>>(hidb, dwb, hdnb);
    // 7) out = x1 + hdn @ fc2_w + fc2_b
    gemm192<1><<<dim3(1, L / 128), 512, G192_SMEM_BYTES>>>(
        hdnb, f2wT, f2b, x1, out, nullptr, nullptr, nullptr, C, HID);
}